// round 10
// baseline (speedup 1.0000x reference)
#include <cuda_runtime.h>
#include <cuda_bf16.h>
#include <cstdint>

// Problem constants (fixed by the dataset)
#define BATCH    2
#define SEQ      2048
#define DMODEL   1024
#define NHEADS   16
#define HEADDIM  64
#define MTOT     (BATCH * SEQ)

// ---------------------------------------------------------------------------
// Scratch (__device__ globals; Q/K/V/AO/Wt/Xt hold tf32-converted bits)
// ---------------------------------------------------------------------------
__device__ uint32_t g_Q [BATCH * NHEADS * SEQ * HEADDIM];
__device__ uint32_t g_K [BATCH * NHEADS * SEQ * HEADDIM];
__device__ uint32_t g_V [BATCH * NHEADS * SEQ * HEADDIM];
__device__ uint32_t g_AO[BATCH * SEQ * DMODEL];
__device__ uint32_t g_Wt[4 * DMODEL * DMODEL];   // transposed weights [N][K], tf32
__device__ uint32_t g_Xt[MTOT * DMODEL];         // x converted to tf32

// ---------------------------------------------------------------------------
// Helpers
// ---------------------------------------------------------------------------
__device__ __forceinline__ uint32_t f32_to_tf32(float f) {
    uint32_t u;
    asm("cvt.rna.tf32.f32 %0, %1;" : "=r"(u) : "f"(f));
    return u;
}

__device__ __forceinline__ void mma_tf32_16x8x8(float c[4], const uint32_t a[4],
                                                const uint32_t b[2]) {
    asm volatile(
        "mma.sync.aligned.m16n8k8.row.col.f32.tf32.tf32.f32 "
        "{%0,%1,%2,%3}, {%4,%5,%6,%7}, {%8,%9}, {%0,%1,%2,%3};"
        : "+f"(c[0]), "+f"(c[1]), "+f"(c[2]), "+f"(c[3])
        : "r"(a[0]), "r"(a[1]), "r"(a[2]), "r"(a[3]), "r"(b[0]), "r"(b[1]));
}

__device__ __forceinline__ uint32_t smem_u32(const void* p) {
    uint32_t a;
    asm("{ .reg .u64 t; cvta.to.shared.u64 t, %1; cvt.u32.u64 %0, t; }" : "=r"(a) : "l"(p));
    return a;
}
__device__ __forceinline__ void cp_async16(uint32_t saddr, const void* gptr) {
    asm volatile("cp.async.ca.shared.global [%0], [%1], 16;" :: "r"(saddr), "l"(gptr));
}
__device__ __forceinline__ void cp_commit() {
    asm volatile("cp.async.commit_group;" ::: "memory");
}
template <int N> __device__ __forceinline__ void cp_wait() {
    asm volatile("cp.async.wait_group %0;" :: "n"(N) : "memory");
}

// ---------------------------------------------------------------------------
// x -> tf32 convert (one pass)
// ---------------------------------------------------------------------------
__global__ void convert_x_kernel(const float* __restrict__ x)
{
    int idx = blockIdx.x * blockDim.x + threadIdx.x;     // float4 index
    float4 v = *(const float4*)(x + idx * 4);
    uint4 o;
    o.x = f32_to_tf32(v.x); o.y = f32_to_tf32(v.y);
    o.z = f32_to_tf32(v.z); o.w = f32_to_tf32(v.w);
    *(uint4*)(g_Xt + idx * 4) = o;
}

// ---------------------------------------------------------------------------
// Transpose + tf32 convert: Wt[n][k] = tf32(W[k][n]) for 4 weights
// ---------------------------------------------------------------------------
__global__ void transpose4_kernel(const float* __restrict__ W0, const float* __restrict__ W1,
                                  const float* __restrict__ W2, const float* __restrict__ W3)
{
    __shared__ float t[32][33];
    const float* src = (blockIdx.z == 0) ? W0 : (blockIdx.z == 1) ? W1
                     : (blockIdx.z == 2) ? W2 : W3;
    uint32_t* dst = g_Wt + (size_t)blockIdx.z * DMODEL * DMODEL;

    int x = blockIdx.x * 32 + threadIdx.x;
    int y = blockIdx.y * 32 + threadIdx.y;
#pragma unroll
    for (int j = 0; j < 32; j += 8)
        t[threadIdx.y + j][threadIdx.x] = src[(size_t)(y + j) * DMODEL + x];
    __syncthreads();
    int x2 = blockIdx.y * 32 + threadIdx.x;
    int y2 = blockIdx.x * 32 + threadIdx.y;
#pragma unroll
    for (int j = 0; j < 32; j += 8)
        dst[(size_t)(y2 + j) * DMODEL + x2] = f32_to_tf32(t[threadIdx.x][threadIdx.y + j]);
}

// ---------------------------------------------------------------------------
// GEMM mainloop shared pieces (2-stage cp.async pipeline) — unchanged (round 9)
// ---------------------------------------------------------------------------
#define KC    32
#define KPAD  36
#define TILEW (128 * KPAD)
#define GEMM_SMEM_BYTES (4 * TILEW * 4)

#define GEMM_PROLOG \
    extern __shared__ uint32_t smw[]; \
    const uint32_t sbase = smem_u32(smw); \
    const int tid = threadIdx.x; \
    const int wid = tid >> 5, lane = tid & 31; \
    const int gid = lane >> 2, ctid = lane & 3; \
    const int warp_m = (wid & 3) * 32, warp_n = (wid >> 2) * 64; \
    const int n0 = blockIdx.x * 128, m0 = blockIdx.y * 128; \
    const int lrow = tid >> 1, lc4a = (tid & 1) * 16;

#define GEMM_PREFETCH(st, kc) do { \
    const uint32_t* Ab_ = A  + (size_t)(m0 + lrow) * DMODEL + (kc) + lc4a; \
    const uint32_t* Bb_ = Bt + (size_t)(n0 + lrow) * DMODEL + (kc) + lc4a; \
    uint32_t sa_ = sbase + ((st) * TILEW + lrow * KPAD + lc4a) * 4; \
    uint32_t sb_ = sbase + ((2 + (st)) * TILEW + lrow * KPAD + lc4a) * 4; \
    _Pragma("unroll") \
    for (int t_ = 0; t_ < 4; t_++) { \
        cp_async16(sa_ + t_ * 16, Ab_ + t_ * 4); \
        cp_async16(sb_ + t_ * 16, Bb_ + t_ * 4); \
    } \
    cp_commit(); \
} while (0)

#define GEMM_COMPUTE(st) do { \
    const uint32_t* Asw = smw + (st) * TILEW; \
    const uint32_t* Bsw = smw + (2 + (st)) * TILEW; \
    _Pragma("unroll") \
    for (int ks = 0; ks < 4; ks++) { \
        const int kb = ks * 8; \
        uint32_t afr[2][4]; \
        _Pragma("unroll") \
        for (int i = 0; i < 2; i++) { \
            const int r = warp_m + i * 16 + gid; \
            afr[i][0] = Asw[(r)     * KPAD + kb + ctid]; \
            afr[i][1] = Asw[(r + 8) * KPAD + kb + ctid]; \
            afr[i][2] = Asw[(r)     * KPAD + kb + ctid + 4]; \
            afr[i][3] = Asw[(r + 8) * KPAD + kb + ctid + 4]; \
        } \
        uint32_t bfr[8][2]; \
        _Pragma("unroll") \
        for (int j = 0; j < 8; j++) { \
            const int cn = warp_n + j * 8 + gid; \
            bfr[j][0] = Bsw[cn * KPAD + kb + ctid]; \
            bfr[j][1] = Bsw[cn * KPAD + kb + ctid + 4]; \
        } \
        _Pragma("unroll") \
        for (int i = 0; i < 2; i++) \
            _Pragma("unroll") \
            for (int j = 0; j < 8; j++) \
                mma_tf32_16x8x8(acc[i][j], afr[i], bfr[j]); \
    } \
} while (0)

#define GEMM_MAINLOOP do { \
    GEMM_PREFETCH(0, 0); \
    for (int kc = 0; kc < 32; kc++) { \
        const int cur = kc & 1; \
        if (kc + 1 < 32) { GEMM_PREFETCH(cur ^ 1, (kc + 1) * KC); cp_wait<1>(); } \
        else             { cp_wait<0>(); } \
        __syncthreads(); \
        GEMM_COMPUTE(cur); \
        __syncthreads(); \
    } \
} while (0)

// ---- QKV projection: grid (8, 32, 3); writes tf32 into [B,H,S,Hd] ----
__global__ __launch_bounds__(256, 1)
void gemm_qkv_kernel(const uint32_t* __restrict__ A, const uint32_t* __restrict__ WtBase,
                     const float* __restrict__ bq, const float* __restrict__ bk,
                     const float* __restrict__ bv,
                     uint32_t* __restrict__ Qo, uint32_t* __restrict__ Ko,
                     uint32_t* __restrict__ Vo)
{
    GEMM_PROLOG
    const int z = blockIdx.z;
    const uint32_t* Bt = WtBase + (size_t)z * DMODEL * DMODEL;
    const float* bias = (z == 0) ? bq : (z == 1) ? bk : bv;
    uint32_t* C = (z == 0) ? Qo : (z == 1) ? Ko : Vo;

    float acc[2][8][4];
#pragma unroll
    for (int i = 0; i < 2; i++)
#pragma unroll
        for (int j = 0; j < 8; j++)
#pragma unroll
            for (int r = 0; r < 4; r++) acc[i][j][r] = 0.0f;

    GEMM_MAINLOOP;

#pragma unroll
    for (int i = 0; i < 2; i++) {
#pragma unroll
        for (int half = 0; half < 2; half++) {
            const int m = m0 + warp_m + i * 16 + gid + half * 8;
            const int b = m >> 11, s = m & 2047;
#pragma unroll
            for (int j = 0; j < 8; j++) {
                const int n = n0 + warp_n + j * 8 + ctid * 2;
                const int h = n >> 6, d0 = n & 63;
                uint32_t* dst = C + ((((size_t)(b * NHEADS + h) * SEQ + s) << 6) + d0);
                dst[0] = f32_to_tf32(acc[i][j][half * 2 + 0] + bias[n]);
                dst[1] = f32_to_tf32(acc[i][j][half * 2 + 1] + bias[n + 1]);
            }
        }
    }
}

// ---- Output projection: row-major fp32 out ----
__global__ __launch_bounds__(256, 1)
void gemm_out_kernel(const uint32_t* __restrict__ A, const uint32_t* __restrict__ Bt,
                     const float* __restrict__ bias, float* __restrict__ C)
{
    GEMM_PROLOG

    float acc[2][8][4];
#pragma unroll
    for (int i = 0; i < 2; i++)
#pragma unroll
        for (int j = 0; j < 8; j++)
#pragma unroll
            for (int r = 0; r < 4; r++) acc[i][j][r] = 0.0f;

    GEMM_MAINLOOP;

#pragma unroll
    for (int i = 0; i < 2; i++) {
#pragma unroll
        for (int half = 0; half < 2; half++) {
            const int m = m0 + warp_m + i * 16 + gid + half * 8;
#pragma unroll
            for (int j = 0; j < 8; j++) {
                const int n = n0 + warp_n + j * 8 + ctid * 2;
                float* dst = C + (size_t)m * DMODEL + n;
                dst[0] = acc[i][j][half * 2 + 0] + bias[n];
                dst[1] = acc[i][j][half * 2 + 1] + bias[n + 1];
            }
        }
    }
}

// ---------------------------------------------------------------------------
// Tensor-core flash attention with ALiBi — fragment-packed smem layouts.
// Grid (16,16,2), 256 threads = 8 warps; warp owns 16 q-rows; 64-key chunks.
//
// Packed-A (Q, P): word addr = wt*1152 + gid*144 + ks*16 + ctid*4 + j,
//   j = half_r + 2*half_c for element (row = wt*16 + half_r*8 + gid,
//   col = ks*8 + half_c*4 + ctid). Reader: one LDS.128 per (ks).
//   gid stride 144 ≡ 16 (mod 32) -> conflict-free 128-bit phases.
// Packed-B K: addr = row*72 + ks*8 + ctid*2 + half_c  (col = ks*8+half_c*4+ctid).
//   Reader: one LDS.64 per (nt,ks). 72 ≡ 8 (mod 32) -> conflict-free.
// Packed-B V: addr = ks*544 + ctid*136 + n*2 + half_k (k-row = ks*8+half_k*4+ctid).
//   Reader: one LDS.64 per (nt,ks). 136 ≡ 8 (mod 32) -> conflict-free.
// ---------------------------------------------------------------------------
#define AQ    128
#define AK    64

#define QP_OFF  0
#define QP_WPW  1152                        // words per warp tile (8*144)
#define KS_OFF  (QP_OFF + 8 * QP_WPW)       //  9216
#define VP_OFF  (KS_OFF + 64 * 72)          // 13824
#define PP_OFF  (VP_OFF + 8 * 544)          // 18176
#define ATTN_SMEM_WORDS (PP_OFF + 8 * QP_WPW)   // 27392
#define ATTN_SMEM_BYTES (ATTN_SMEM_WORDS * 4)   // 109,568 B

__global__ __launch_bounds__(256, 2)
void attn_mma_kernel(const uint32_t* __restrict__ Q, const uint32_t* __restrict__ K,
                     const uint32_t* __restrict__ V, uint32_t* __restrict__ AO)
{
    extern __shared__ uint32_t smw[];
    uint32_t* Qp = smw + QP_OFF;
    uint32_t* Ks = smw + KS_OFF;
    uint32_t* Vp = smw + VP_OFF;
    uint32_t* Pp = smw + PP_OFF;

    const int tid  = threadIdx.x;
    const int wid  = tid >> 5;
    const int lane = tid & 31;
    const int gid  = lane >> 2;
    const int ctid = lane & 3;

    const int qt = blockIdx.x;
    const int h  = blockIdx.y;
    const int b  = blockIdx.z;
    const int q0 = qt * AQ;

    const uint32_t* Qb = Q + (((size_t)(b * NHEADS + h) * SEQ + q0) << 6);
    const uint32_t* Kb = K + (((size_t)(b * NHEADS + h) * SEQ) << 6);
    const uint32_t* Vb = V + (((size_t)(b * NHEADS + h) * SEQ) << 6);

    // ---- load Q tile (128x64) into packed-A layout ----
#pragma unroll
    for (int t = 0; t < 8; t++) {
        int idx = tid + t * 256;                 // uint4 idx, 0..2047
        int row = idx >> 4;
        int c4  = (idx & 15) * 4;
        uint4 v4 = *(const uint4*)(Qb + row * HEADDIM + c4);
        const int wt = row >> 4, rr = row & 15;
        const int base = wt * QP_WPW + (rr & 7) * 144 + (c4 >> 3) * 16
                       + ((c4 & 4) >> 1) + (rr >> 3);       // +2*half_c + half_r
        Qp[base +  0] = v4.x;
        Qp[base +  4] = v4.y;
        Qp[base +  8] = v4.z;
        Qp[base + 12] = v4.w;
    }

    const float slope = exp2f(-(float)h / (float)NHEADS);
    const float scale = 0.125f;
    const float qg0 = (float)(q0 + wid * 16 + gid);
    const float qg1 = qg0 + 8.0f;

    const int aBase = wid * QP_WPW + gid * 144 + ctid * 4;   // packed-A read base

    float oacc[8][4];
#pragma unroll
    for (int j = 0; j < 8; j++)
#pragma unroll
        for (int r = 0; r < 4; r++) oacc[j][r] = 0.0f;
    float m0 = -1e30f, m1 = -1e30f, l0 = 0.0f, l1 = 0.0f;

    for (int kt = 0; kt < SEQ; kt += AK) {
        __syncthreads();
        // ---- load K,V chunk (64x64 each) into packed-B layouts ----
#pragma unroll
        for (int t = 0; t < 4; t++) {
            int idx = tid + t * 256;             // uint4 idx, 0..1023
            int row = idx >> 4;
            int c4  = (idx & 15) * 4;
            uint4 kv = *(const uint4*)(Kb + (size_t)(kt + row) * HEADDIM + c4);
            const int kbase = row * 72 + (c4 >> 3) * 8 + ((c4 & 4) >> 2);
            Ks[kbase + 0] = kv.x;
            Ks[kbase + 2] = kv.y;
            Ks[kbase + 4] = kv.z;
            Ks[kbase + 6] = kv.w;
            uint4 vv = *(const uint4*)(Vb + (size_t)(kt + row) * HEADDIM + c4);
            const int w = row & 7;
            const int vbase = (row >> 3) * 544 + (w & 3) * 136 + (w >> 2) + c4 * 2;
            Vp[vbase + 0] = vv.x;
            Vp[vbase + 2] = vv.y;
            Vp[vbase + 4] = vv.z;
            Vp[vbase + 6] = vv.w;
        }
        __syncthreads();

        // ---- S = Q K^T ----
        float sacc[8][4];
#pragma unroll
        for (int j = 0; j < 8; j++)
#pragma unroll
            for (int r = 0; r < 4; r++) sacc[j][r] = 0.0f;

#pragma unroll
        for (int ks = 0; ks < 8; ks++) {
            uint32_t a[4];
            *(uint4*)a = *(const uint4*)&Qp[aBase + ks * 16];
#pragma unroll
            for (int nt = 0; nt < 8; nt++) {
                uint32_t bf[2];
                *(uint2*)bf = *(const uint2*)&Ks[(nt * 8 + gid) * 72 + ks * 8 + ctid * 2];
                mma_tf32_16x8x8(sacc[nt], a, bf);
            }
        }

        // ---- ALiBi + scale + row max ----
        float mx0 = -1e30f, mx1 = -1e30f;
#pragma unroll
        for (int nt = 0; nt < 8; nt++) {
            const float kg = (float)(kt + nt * 8 + 2 * ctid);
            sacc[nt][0] = sacc[nt][0] * scale + slope * (kg        - qg0);
            sacc[nt][1] = sacc[nt][1] * scale + slope * (kg + 1.0f - qg0);
            sacc[nt][2] = sacc[nt][2] * scale + slope * (kg        - qg1);
            sacc[nt][3] = sacc[nt][3] * scale + slope * (kg + 1.0f - qg1);
            mx0 = fmaxf(mx0, fmaxf(sacc[nt][0], sacc[nt][1]));
            mx1 = fmaxf(mx1, fmaxf(sacc[nt][2], sacc[nt][3]));
        }
#pragma unroll
        for (int msk = 1; msk < 4; msk <<= 1) {
            mx0 = fmaxf(mx0, __shfl_xor_sync(0xffffffffu, mx0, msk));
            mx1 = fmaxf(mx1, __shfl_xor_sync(0xffffffffu, mx1, msk));
        }

        const float m0n = fmaxf(m0, mx0);
        const float m1n = fmaxf(m1, mx1);
        const float corr0 = __expf(m0 - m0n);
        const float corr1 = __expf(m1 - m1n);
        m0 = m0n; m1 = m1n;

        // ---- P = exp(S - m) -> warp-private packed-A rows (tf32) ----
        // cols c = nt*8 + 2*ctid (+1): slot*4 = 8*(ctid&1), half_c = ctid>>1.
        const int pBase = wid * QP_WPW + gid * 144 + 8 * (ctid & 1) + 2 * (ctid >> 1);
        float ps0 = 0.0f, ps1 = 0.0f;
#pragma unroll
        for (int nt = 0; nt < 8; nt++) {
            float p0 = __expf(sacc[nt][0] - m0);
            float p1 = __expf(sacc[nt][1] - m0);
            float p2 = __expf(sacc[nt][2] - m1);
            float p3 = __expf(sacc[nt][3] - m1);
            ps0 += p0 + p1;
            ps1 += p2 + p3;
            // (p0,p2) at j=0,1 ; (p1,p3) at j=0,1 of slot+1 (addr+4)
            *(uint2*)&Pp[pBase + nt * 16]     = make_uint2(f32_to_tf32(p0), f32_to_tf32(p2));
            *(uint2*)&Pp[pBase + nt * 16 + 4] = make_uint2(f32_to_tf32(p1), f32_to_tf32(p3));
        }
#pragma unroll
        for (int msk = 1; msk < 4; msk <<= 1) {
            ps0 += __shfl_xor_sync(0xffffffffu, ps0, msk);
            ps1 += __shfl_xor_sync(0xffffffffu, ps1, msk);
        }
        l0 = l0 * corr0 + ps0;
        l1 = l1 * corr1 + ps1;

#pragma unroll
        for (int nt = 0; nt < 8; nt++) {
            oacc[nt][0] *= corr0; oacc[nt][1] *= corr0;
            oacc[nt][2] *= corr1; oacc[nt][3] *= corr1;
        }
        __syncwarp();   // Pp rows are warp-private

        // ---- O += P V ----
        const int pABase = wid * QP_WPW + gid * 144 + ctid * 4;
#pragma unroll
        for (int ks = 0; ks < 8; ks++) {
            uint32_t a[4];
            *(uint4*)a = *(const uint4*)&Pp[pABase + ks * 16];
#pragma unroll
            for (int nt = 0; nt < 8; nt++) {
                uint32_t bf[2];
                *(uint2*)bf = *(const uint2*)&Vp[ks * 544 + ctid * 136 + (nt * 8 + gid) * 2];
                mma_tf32_16x8x8(oacc[nt], a, bf);
            }
        }
    }

    // ---- normalize, convert to tf32, write AO ----
    const float inv0 = 1.0f / l0;
    const float inv1 = 1.0f / l1;
    const int qr0 = q0 + wid * 16 + gid;
    const int qr1 = qr0 + 8;
    uint32_t* dst0 = AO + ((size_t)(b * SEQ + qr0) * DMODEL) + h * HEADDIM;
    uint32_t* dst1 = AO + ((size_t)(b * SEQ + qr1) * DMODEL) + h * HEADDIM;
#pragma unroll
    for (int nt = 0; nt < 8; nt++) {
        const int col = nt * 8 + 2 * ctid;
        *(uint2*)(dst0 + col) = make_uint2(f32_to_tf32(oacc[nt][0] * inv0),
                                           f32_to_tf32(oacc[nt][1] * inv0));
        *(uint2*)(dst1 + col) = make_uint2(f32_to_tf32(oacc[nt][2] * inv1),
                                           f32_to_tf32(oacc[nt][3] * inv1));
    }
}

// ---------------------------------------------------------------------------
// Launcher
// ---------------------------------------------------------------------------
extern "C" void kernel_launch(void* const* d_in, const int* in_sizes, int n_in,
                              void* d_out, int out_size)
{
    const float* x  = (const float*)d_in[0];
    const float* Wq = (const float*)d_in[1];
    const float* bq = (const float*)d_in[2];
    const float* Wk = (const float*)d_in[3];
    const float* bk = (const float*)d_in[4];
    const float* Wv = (const float*)d_in[5];
    const float* bv = (const float*)d_in[6];
    const float* Wo = (const float*)d_in[7];
    const float* bo = (const float*)d_in[8];
    float* out = (float*)d_out;

    uint32_t *gQ, *gK, *gV, *gAO, *gWt, *gXt;
    cudaGetSymbolAddress((void**)&gQ,  g_Q);
    cudaGetSymbolAddress((void**)&gK,  g_K);
    cudaGetSymbolAddress((void**)&gV,  g_V);
    cudaGetSymbolAddress((void**)&gAO, g_AO);
    cudaGetSymbolAddress((void**)&gWt, g_Wt);
    cudaGetSymbolAddress((void**)&gXt, g_Xt);

    cudaFuncSetAttribute(gemm_qkv_kernel, cudaFuncAttributeMaxDynamicSharedMemorySize,
                         GEMM_SMEM_BYTES);
    cudaFuncSetAttribute(gemm_out_kernel, cudaFuncAttributeMaxDynamicSharedMemorySize,
                         GEMM_SMEM_BYTES);
    cudaFuncSetAttribute(attn_mma_kernel, cudaFuncAttributeMaxDynamicSharedMemorySize,
                         ATTN_SMEM_BYTES);

    // Prep: weight transpose+convert, x convert
    transpose4_kernel<<<dim3(DMODEL / 32, DMODEL / 32, 4), dim3(32, 8)>>>(Wq, Wk, Wv, Wo);
    convert_x_kernel<<<(MTOT * DMODEL / 4) / 256, 256>>>(x);

    // QKV projections (one launch, grid.z selects head)
    dim3 qkvgrid(DMODEL / 128, MTOT / 128, 3);   // (8, 32, 3)
    gemm_qkv_kernel<<<qkvgrid, 256, GEMM_SMEM_BYTES>>>(gXt, gWt, bq, bk, bv, gQ, gK, gV);

    // Attention
    dim3 agrid(SEQ / AQ, NHEADS, BATCH);         // (16, 16, 2)
    attn_mma_kernel<<<agrid, 256, ATTN_SMEM_BYTES>>>(gQ, gK, gV, gAO);

    // Output projection
    dim3 ogrid(DMODEL / 128, MTOT / 128);        // (8, 32)
    gemm_out_kernel<<<ogrid, 256, GEMM_SMEM_BYTES>>>(gAO, gWt + 3 * (size_t)DMODEL * DMODEL,
                                                     bo, out);
}

// round 11
// speedup vs baseline: 1.4586x; 1.4586x over previous
#include <cuda_runtime.h>
#include <cuda_fp16.h>
#include <cstdint>

// Problem constants (fixed by the dataset)
#define BATCH    2
#define SEQ      2048
#define DMODEL   1024
#define NHEADS   16
#define HEADDIM  64
#define MTOT     (BATCH * SEQ)

// ---------------------------------------------------------------------------
// Scratch (__device__ globals)
// Q/K/V/AO: tf32 words (attention contract, unchanged from round 9)
// Wt/Xt: fp16, packed 2-per-word along K
// ---------------------------------------------------------------------------
__device__ uint32_t g_Q [BATCH * NHEADS * SEQ * HEADDIM];
__device__ uint32_t g_K [BATCH * NHEADS * SEQ * HEADDIM];
__device__ uint32_t g_V [BATCH * NHEADS * SEQ * HEADDIM];
__device__ uint32_t g_AO[BATCH * SEQ * DMODEL];
__device__ uint32_t g_Wt[4 * DMODEL * DMODEL / 2];   // [N][K/2] fp16x2 per matrix
__device__ uint32_t g_Xt[MTOT * DMODEL / 2];         // [M][K/2] fp16x2

// ---------------------------------------------------------------------------
// Helpers
// ---------------------------------------------------------------------------
__device__ __forceinline__ uint32_t f32_to_tf32(float f) {
    uint32_t u;
    asm("cvt.rna.tf32.f32 %0, %1;" : "=r"(u) : "f"(f));
    return u;
}

// tf32: D += A(16x8) @ B(8x8)
__device__ __forceinline__ void mma_tf32_16x8x8(float c[4], const uint32_t a[4],
                                                const uint32_t b[2]) {
    asm volatile(
        "mma.sync.aligned.m16n8k8.row.col.f32.tf32.tf32.f32 "
        "{%0,%1,%2,%3}, {%4,%5,%6,%7}, {%8,%9}, {%0,%1,%2,%3};"
        : "+f"(c[0]), "+f"(c[1]), "+f"(c[2]), "+f"(c[3])
        : "r"(a[0]), "r"(a[1]), "r"(a[2]), "r"(a[3]), "r"(b[0]), "r"(b[1]));
}

// fp16: D += A(16x16) @ B(16x8), fp32 accumulate
__device__ __forceinline__ void mma_f16_16x8x16(float c[4], const uint32_t a[4],
                                                const uint32_t b[2]) {
    asm volatile(
        "mma.sync.aligned.m16n8k16.row.col.f32.f16.f16.f32 "
        "{%0,%1,%2,%3}, {%4,%5,%6,%7}, {%8,%9}, {%0,%1,%2,%3};"
        : "+f"(c[0]), "+f"(c[1]), "+f"(c[2]), "+f"(c[3])
        : "r"(a[0]), "r"(a[1]), "r"(a[2]), "r"(a[3]), "r"(b[0]), "r"(b[1]));
}

__device__ __forceinline__ uint32_t smem_u32(const void* p) {
    uint32_t a;
    asm("{ .reg .u64 t; cvta.to.shared.u64 t, %1; cvt.u32.u64 %0, t; }" : "=r"(a) : "l"(p));
    return a;
}
__device__ __forceinline__ void cp_async16(uint32_t saddr, const void* gptr) {
    asm volatile("cp.async.ca.shared.global [%0], [%1], 16;" :: "r"(saddr), "l"(gptr));
}
__device__ __forceinline__ void cp_commit() {
    asm volatile("cp.async.commit_group;" ::: "memory");
}
template <int N> __device__ __forceinline__ void cp_wait() {
    asm volatile("cp.async.wait_group %0;" :: "n"(N) : "memory");
}

// ---------------------------------------------------------------------------
// x -> fp16 convert (one pass): 4 floats -> 2 packed words per thread
// ---------------------------------------------------------------------------
__global__ void convert_x_kernel(const float* __restrict__ x)
{
    int idx = blockIdx.x * blockDim.x + threadIdx.x;     // float4 index
    float4 v = *(const float4*)(x + idx * 4);
    __half2 h0 = __floats2half2_rn(v.x, v.y);
    __half2 h1 = __floats2half2_rn(v.z, v.w);
    uint2 o = make_uint2(*(uint32_t*)&h0, *(uint32_t*)&h1);
    *(uint2*)(g_Xt + idx * 2) = o;
}

// ---------------------------------------------------------------------------
// Transpose + fp16 convert: Wt[n][k] = fp16(W[k][n]) for 4 weights
// ---------------------------------------------------------------------------
__global__ void transpose4_kernel(const float* __restrict__ W0, const float* __restrict__ W1,
                                  const float* __restrict__ W2, const float* __restrict__ W3)
{
    __shared__ float t[32][33];
    const float* src = (blockIdx.z == 0) ? W0 : (blockIdx.z == 1) ? W1
                     : (blockIdx.z == 2) ? W2 : W3;
    __half* dst = (__half*)(g_Wt + (size_t)blockIdx.z * (DMODEL * DMODEL / 2));

    int x = blockIdx.x * 32 + threadIdx.x;
    int y = blockIdx.y * 32 + threadIdx.y;
#pragma unroll
    for (int j = 0; j < 32; j += 8)
        t[threadIdx.y + j][threadIdx.x] = src[(size_t)(y + j) * DMODEL + x];
    __syncthreads();
    int x2 = blockIdx.y * 32 + threadIdx.x;
    int y2 = blockIdx.x * 32 + threadIdx.y;
#pragma unroll
    for (int j = 0; j < 32; j += 8)
        dst[(size_t)(y2 + j) * DMODEL + x2] = __float2half_rn(t[threadIdx.x][threadIdx.y + j]);
}

// ---------------------------------------------------------------------------
// fp16 GEMM mainloop (2-stage cp.async pipeline)
// CTA 128x128, 256 threads = 8 warps (4M x 2N), warp tile 32x64.
// K-chunk 32 elements = 16 words; 2 k-steps of m16n8k16 per chunk.
// Smem tile [128][WPAD=20] words; gathers conflict-free (20 ≡ 20 mod 32).
// ---------------------------------------------------------------------------
#define KWORDS 16
#define WPAD   20
#define TILEW  (128 * WPAD)                 // 2560 words per tile
#define GEMM_SMEM_BYTES (4 * TILEW * 4)     // 2 stages x (A+B) = 40,960 B

#define GEMM_PROLOG \
    extern __shared__ uint32_t smw[]; \
    const uint32_t sbase = smem_u32(smw); \
    const int tid = threadIdx.x; \
    const int wid = tid >> 5, lane = tid & 31; \
    const int gid = lane >> 2, ctid = lane & 3; \
    const int warp_m = (wid & 3) * 32, warp_n = (wid >> 2) * 64; \
    const int n0 = blockIdx.x * 128, m0 = blockIdx.y * 128; \
    const int lrow = tid >> 1, lcw = (tid & 1) * 8;

// prefetch stage st, k word-offset kcw (row stride in gmem = DMODEL/2 words)
#define GEMM_PREFETCH(st, kcw) do { \
    const uint32_t* Ab_ = A  + (size_t)(m0 + lrow) * (DMODEL / 2) + (kcw) + lcw; \
    const uint32_t* Bb_ = Bt + (size_t)(n0 + lrow) * (DMODEL / 2) + (kcw) + lcw; \
    uint32_t sa_ = sbase + ((st) * TILEW + lrow * WPAD + lcw) * 4; \
    uint32_t sb_ = sbase + ((2 + (st)) * TILEW + lrow * WPAD + lcw) * 4; \
    cp_async16(sa_,      Ab_);     \
    cp_async16(sa_ + 16, Ab_ + 4); \
    cp_async16(sb_,      Bb_);     \
    cp_async16(sb_ + 16, Bb_ + 4); \
    cp_commit(); \
} while (0)

#define GEMM_COMPUTE(st) do { \
    const uint32_t* Asw = smw + (st) * TILEW; \
    const uint32_t* Bsw = smw + (2 + (st)) * TILEW; \
    _Pragma("unroll") \
    for (int ks = 0; ks < 2; ks++) { \
        const int kb = ks * 8; \
        uint32_t afr[2][4]; \
        _Pragma("unroll") \
        for (int i = 0; i < 2; i++) { \
            const int r = warp_m + i * 16 + gid; \
            afr[i][0] = Asw[(r)     * WPAD + kb + ctid]; \
            afr[i][1] = Asw[(r + 8) * WPAD + kb + ctid]; \
            afr[i][2] = Asw[(r)     * WPAD + kb + ctid + 4]; \
            afr[i][3] = Asw[(r + 8) * WPAD + kb + ctid + 4]; \
        } \
        uint32_t bfr[8][2]; \
        _Pragma("unroll") \
        for (int j = 0; j < 8; j++) { \
            const int cn = warp_n + j * 8 + gid; \
            bfr[j][0] = Bsw[cn * WPAD + kb + ctid]; \
            bfr[j][1] = Bsw[cn * WPAD + kb + ctid + 4]; \
        } \
        _Pragma("unroll") \
        for (int i = 0; i < 2; i++) \
            _Pragma("unroll") \
            for (int j = 0; j < 8; j++) \
                mma_f16_16x8x16(acc[i][j], afr[i], bfr[j]); \
    } \
} while (0)

#define GEMM_MAINLOOP do { \
    GEMM_PREFETCH(0, 0); \
    for (int kc = 0; kc < 32; kc++) { \
        const int cur = kc & 1; \
        if (kc + 1 < 32) { GEMM_PREFETCH(cur ^ 1, (kc + 1) * KWORDS); cp_wait<1>(); } \
        else             { cp_wait<0>(); } \
        __syncthreads(); \
        GEMM_COMPUTE(cur); \
        __syncthreads(); \
    } \
} while (0)

// ---- QKV projection: grid (8, 32, 3); writes tf32 into [B,H,S,Hd] ----
__global__ __launch_bounds__(256, 1)
void gemm_qkv_kernel(const uint32_t* __restrict__ A, const uint32_t* __restrict__ WtBase,
                     const float* __restrict__ bq, const float* __restrict__ bk,
                     const float* __restrict__ bv,
                     uint32_t* __restrict__ Qo, uint32_t* __restrict__ Ko,
                     uint32_t* __restrict__ Vo)
{
    GEMM_PROLOG
    const int z = blockIdx.z;
    const uint32_t* Bt = WtBase + (size_t)z * (DMODEL * DMODEL / 2);
    const float* bias = (z == 0) ? bq : (z == 1) ? bk : bv;
    uint32_t* C = (z == 0) ? Qo : (z == 1) ? Ko : Vo;

    float acc[2][8][4];
#pragma unroll
    for (int i = 0; i < 2; i++)
#pragma unroll
        for (int j = 0; j < 8; j++)
#pragma unroll
            for (int r = 0; r < 4; r++) acc[i][j][r] = 0.0f;

    GEMM_MAINLOOP;

#pragma unroll
    for (int i = 0; i < 2; i++) {
#pragma unroll
        for (int half = 0; half < 2; half++) {
            const int m = m0 + warp_m + i * 16 + gid + half * 8;
            const int b = m >> 11, s = m & 2047;
#pragma unroll
            for (int j = 0; j < 8; j++) {
                const int n = n0 + warp_n + j * 8 + ctid * 2;
                const int h = n >> 6, d0 = n & 63;
                uint32_t* dst = C + ((((size_t)(b * NHEADS + h) * SEQ + s) << 6) + d0);
                dst[0] = f32_to_tf32(acc[i][j][half * 2 + 0] + bias[n]);
                dst[1] = f32_to_tf32(acc[i][j][half * 2 + 1] + bias[n + 1]);
            }
        }
    }
}

// ---- Output projection: row-major fp32 out ----
__global__ __launch_bounds__(256, 1)
void gemm_out_kernel(const uint32_t* __restrict__ A, const uint32_t* __restrict__ Bt,
                     const float* __restrict__ bias, float* __restrict__ C)
{
    GEMM_PROLOG

    float acc[2][8][4];
#pragma unroll
    for (int i = 0; i < 2; i++)
#pragma unroll
        for (int j = 0; j < 8; j++)
#pragma unroll
            for (int r = 0; r < 4; r++) acc[i][j][r] = 0.0f;

    GEMM_MAINLOOP;

#pragma unroll
    for (int i = 0; i < 2; i++) {
#pragma unroll
        for (int half = 0; half < 2; half++) {
            const int m = m0 + warp_m + i * 16 + gid + half * 8;
#pragma unroll
            for (int j = 0; j < 8; j++) {
                const int n = n0 + warp_n + j * 8 + ctid * 2;
                float* dst = C + (size_t)m * DMODEL + n;
                dst[0] = acc[i][j][half * 2 + 0] + bias[n];
                dst[1] = acc[i][j][half * 2 + 1] + bias[n + 1];
            }
        }
    }
}

// ---- AO -> fp16 packed convert (for out-proj A operand) ----
__global__ void convert_ao_kernel(const uint32_t* __restrict__ AO, uint32_t* __restrict__ AOh)
{
    int idx = blockIdx.x * blockDim.x + threadIdx.x;     // uint4 index (4 tf32 words)
    uint4 v = *(const uint4*)(AO + idx * 4);
    __half2 h0 = __floats2half2_rn(__uint_as_float(v.x), __uint_as_float(v.y));
    __half2 h1 = __floats2half2_rn(__uint_as_float(v.z), __uint_as_float(v.w));
    *(uint2*)(AOh + idx * 2) = make_uint2(*(uint32_t*)&h0, *(uint32_t*)&h1);
}
__device__ uint32_t g_AOh[MTOT * DMODEL / 2];    // AO as fp16 pairs

// ---------------------------------------------------------------------------
// Tensor-core flash attention with ALiBi (mma.sync tf32) — EXACT round-9 code.
// Grid (16,16,2), 256 threads = 8 warps, warp owns 16 q-rows. 64-key chunks.
// Pads: Qs/Ks/Ps 68 (row-gathers conflict-free), Vs 72 (col-gather c-free).
// ---------------------------------------------------------------------------
#define AQ    128
#define AK    64
#define QPW   68
#define VPW   72

#define AQS_OFF 0
#define AKS_OFF (AQ * QPW)                    //  8704
#define AVS_OFF (AKS_OFF + AK * QPW)          // 13056
#define APS_OFF (AVS_OFF + AK * VPW)          // 17664
#define ATTN_SMEM_WORDS (APS_OFF + AQ * QPW)  // 26368
#define ATTN_SMEM_BYTES (ATTN_SMEM_WORDS * 4) // 105,472 B

__global__ __launch_bounds__(256, 2)
void attn_mma_kernel(const uint32_t* __restrict__ Q, const uint32_t* __restrict__ K,
                     const uint32_t* __restrict__ V, uint32_t* __restrict__ AO)
{
    extern __shared__ uint32_t smw[];
    uint32_t* Qs = smw + AQS_OFF;
    uint32_t* Ks = smw + AKS_OFF;
    uint32_t* Vs = smw + AVS_OFF;
    uint32_t* Ps = smw + APS_OFF;

    const int tid  = threadIdx.x;
    const int wid  = tid >> 5;
    const int lane = tid & 31;
    const int gid  = lane >> 2;
    const int ctid = lane & 3;
    const int wrow = wid * 16;

    const int qt = blockIdx.x;
    const int h  = blockIdx.y;
    const int b  = blockIdx.z;
    const int q0 = qt * AQ;

    const uint32_t* Qb = Q + (((size_t)(b * NHEADS + h) * SEQ + q0) << 6);
    const uint32_t* Kb = K + (((size_t)(b * NHEADS + h) * SEQ) << 6);
    const uint32_t* Vb = V + (((size_t)(b * NHEADS + h) * SEQ) << 6);

    // ---- load Q tile (128x64, already tf32) ----
#pragma unroll
    for (int t = 0; t < 8; t++) {
        int idx = tid + t * 256;
        int row = idx >> 4;
        int c4  = (idx & 15) * 4;
        *(uint4*)&Qs[row * QPW + c4] = *(const uint4*)(Qb + row * HEADDIM + c4);
    }

    const float slope = exp2f(-(float)h / (float)NHEADS);
    const float scale = 0.125f;
    const float qg0 = (float)(q0 + wrow + gid);
    const float qg1 = qg0 + 8.0f;

    float oacc[8][4];
#pragma unroll
    for (int j = 0; j < 8; j++)
#pragma unroll
        for (int r = 0; r < 4; r++) oacc[j][r] = 0.0f;
    float m0 = -1e30f, m1 = -1e30f, l0 = 0.0f, l1 = 0.0f;

    for (int kt = 0; kt < SEQ; kt += AK) {
        __syncthreads();
        // ---- load K,V chunk (raw tf32) ----
#pragma unroll
        for (int t = 0; t < 4; t++) {
            int idx = tid + t * 256;
            int row = idx >> 4;
            int c4  = (idx & 15) * 4;
            *(uint4*)&Ks[row * QPW + c4] = *(const uint4*)(Kb + (size_t)(kt + row) * HEADDIM + c4);
            *(uint4*)&Vs[row * VPW + c4] = *(const uint4*)(Vb + (size_t)(kt + row) * HEADDIM + c4);
        }
        __syncthreads();

        // ---- S = Q K^T ----
        float sacc[8][4];
#pragma unroll
        for (int j = 0; j < 8; j++)
#pragma unroll
            for (int r = 0; r < 4; r++) sacc[j][r] = 0.0f;

#pragma unroll
        for (int ks = 0; ks < 8; ks++) {
            const int kb = ks * 8;
            uint32_t a[4];
            a[0] = Qs[(wrow + gid)     * QPW + kb + ctid];
            a[1] = Qs[(wrow + gid + 8) * QPW + kb + ctid];
            a[2] = Qs[(wrow + gid)     * QPW + kb + ctid + 4];
            a[3] = Qs[(wrow + gid + 8) * QPW + kb + ctid + 4];
#pragma unroll
            for (int nt = 0; nt < 8; nt++) {
                uint32_t bf[2];
                bf[0] = Ks[(nt * 8 + gid) * QPW + kb + ctid];
                bf[1] = Ks[(nt * 8 + gid) * QPW + kb + ctid + 4];
                mma_tf32_16x8x8(sacc[nt], a, bf);
            }
        }

        // ---- ALiBi + scale + row max ----
        float mx0 = -1e30f, mx1 = -1e30f;
#pragma unroll
        for (int nt = 0; nt < 8; nt++) {
            const float kg = (float)(kt + nt * 8 + 2 * ctid);
            sacc[nt][0] = sacc[nt][0] * scale + slope * (kg        - qg0);
            sacc[nt][1] = sacc[nt][1] * scale + slope * (kg + 1.0f - qg0);
            sacc[nt][2] = sacc[nt][2] * scale + slope * (kg        - qg1);
            sacc[nt][3] = sacc[nt][3] * scale + slope * (kg + 1.0f - qg1);
            mx0 = fmaxf(mx0, fmaxf(sacc[nt][0], sacc[nt][1]));
            mx1 = fmaxf(mx1, fmaxf(sacc[nt][2], sacc[nt][3]));
        }
#pragma unroll
        for (int msk = 1; msk < 4; msk <<= 1) {
            mx0 = fmaxf(mx0, __shfl_xor_sync(0xffffffffu, mx0, msk));
            mx1 = fmaxf(mx1, __shfl_xor_sync(0xffffffffu, mx1, msk));
        }

        const float m0n = fmaxf(m0, mx0);
        const float m1n = fmaxf(m1, mx1);
        const float corr0 = __expf(m0 - m0n);
        const float corr1 = __expf(m1 - m1n);
        m0 = m0n; m1 = m1n;

        // ---- P = exp(S - m) -> warp-private Ps rows (tf32) ----
        float ps0 = 0.0f, ps1 = 0.0f;
        const int r0 = wrow + gid, r1 = wrow + gid + 8;
#pragma unroll
        for (int nt = 0; nt < 8; nt++) {
            const int col = nt * 8 + 2 * ctid;
            float p0 = __expf(sacc[nt][0] - m0);
            float p1 = __expf(sacc[nt][1] - m0);
            float p2 = __expf(sacc[nt][2] - m1);
            float p3 = __expf(sacc[nt][3] - m1);
            ps0 += p0 + p1;
            ps1 += p2 + p3;
            *(uint2*)&Ps[r0 * QPW + col] = make_uint2(f32_to_tf32(p0), f32_to_tf32(p1));
            *(uint2*)&Ps[r1 * QPW + col] = make_uint2(f32_to_tf32(p2), f32_to_tf32(p3));
        }
#pragma unroll
        for (int msk = 1; msk < 4; msk <<= 1) {
            ps0 += __shfl_xor_sync(0xffffffffu, ps0, msk);
            ps1 += __shfl_xor_sync(0xffffffffu, ps1, msk);
        }
        l0 = l0 * corr0 + ps0;
        l1 = l1 * corr1 + ps1;

#pragma unroll
        for (int nt = 0; nt < 8; nt++) {
            oacc[nt][0] *= corr0; oacc[nt][1] *= corr0;
            oacc[nt][2] *= corr1; oacc[nt][3] *= corr1;
        }
        __syncwarp();

        // ---- O += P V ----
#pragma unroll
        for (int ks = 0; ks < 8; ks++) {
            const int kb = ks * 8;
            uint32_t a[4];
            a[0] = Ps[(wrow + gid)     * QPW + kb + ctid];
            a[1] = Ps[(wrow + gid + 8) * QPW + kb + ctid];
            a[2] = Ps[(wrow + gid)     * QPW + kb + ctid + 4];
            a[3] = Ps[(wrow + gid + 8) * QPW + kb + ctid + 4];
#pragma unroll
            for (int nt = 0; nt < 8; nt++) {
                uint32_t bf[2];
                bf[0] = Vs[(kb + ctid)     * VPW + nt * 8 + gid];
                bf[1] = Vs[(kb + ctid + 4) * VPW + nt * 8 + gid];
                mma_tf32_16x8x8(oacc[nt], a, bf);
            }
        }
    }

    // ---- normalize, convert to tf32, write AO ----
    const float inv0 = 1.0f / l0;
    const float inv1 = 1.0f / l1;
    const int qr0 = q0 + wrow + gid;
    const int qr1 = qr0 + 8;
    uint32_t* dst0 = AO + ((size_t)(b * SEQ + qr0) * DMODEL) + h * HEADDIM;
    uint32_t* dst1 = AO + ((size_t)(b * SEQ + qr1) * DMODEL) + h * HEADDIM;
#pragma unroll
    for (int nt = 0; nt < 8; nt++) {
        const int col = nt * 8 + 2 * ctid;
        *(uint2*)(dst0 + col) = make_uint2(f32_to_tf32(oacc[nt][0] * inv0),
                                           f32_to_tf32(oacc[nt][1] * inv0));
        *(uint2*)(dst1 + col) = make_uint2(f32_to_tf32(oacc[nt][2] * inv1),
                                           f32_to_tf32(oacc[nt][3] * inv1));
    }
}

// ---------------------------------------------------------------------------
// Launcher
// ---------------------------------------------------------------------------
extern "C" void kernel_launch(void* const* d_in, const int* in_sizes, int n_in,
                              void* d_out, int out_size)
{
    const float* x  = (const float*)d_in[0];
    const float* Wq = (const float*)d_in[1];
    const float* bq = (const float*)d_in[2];
    const float* Wk = (const float*)d_in[3];
    const float* bk = (const float*)d_in[4];
    const float* Wv = (const float*)d_in[5];
    const float* bv = (const float*)d_in[6];
    const float* Wo = (const float*)d_in[7];
    const float* bo = (const float*)d_in[8];
    float* out = (float*)d_out;

    uint32_t *gQ, *gK, *gV, *gAO, *gAOh, *gWt, *gXt;
    cudaGetSymbolAddress((void**)&gQ,   g_Q);
    cudaGetSymbolAddress((void**)&gK,   g_K);
    cudaGetSymbolAddress((void**)&gV,   g_V);
    cudaGetSymbolAddress((void**)&gAO,  g_AO);
    cudaGetSymbolAddress((void**)&gAOh, g_AOh);
    cudaGetSymbolAddress((void**)&gWt,  g_Wt);
    cudaGetSymbolAddress((void**)&gXt,  g_Xt);

    cudaFuncSetAttribute(gemm_qkv_kernel, cudaFuncAttributeMaxDynamicSharedMemorySize,
                         GEMM_SMEM_BYTES);
    cudaFuncSetAttribute(gemm_out_kernel, cudaFuncAttributeMaxDynamicSharedMemorySize,
                         GEMM_SMEM_BYTES);
    cudaFuncSetAttribute(attn_mma_kernel, cudaFuncAttributeMaxDynamicSharedMemorySize,
                         ATTN_SMEM_BYTES);

    // Prep: weight transpose+convert (fp16), x convert (fp16)
    transpose4_kernel<<<dim3(DMODEL / 32, DMODEL / 32, 4), dim3(32, 8)>>>(Wq, Wk, Wv, Wo);
    convert_x_kernel<<<(MTOT * DMODEL / 4) / 256, 256>>>(x);

    // QKV projections (one launch, grid.z selects matrix); outputs tf32
    dim3 qkvgrid(DMODEL / 128, MTOT / 128, 3);   // (8, 32, 3)
    gemm_qkv_kernel<<<qkvgrid, 256, GEMM_SMEM_BYTES>>>(gXt, gWt, bq, bk, bv, gQ, gK, gV);

    // Attention (round-9 tf32 version)
    dim3 agrid(SEQ / AQ, NHEADS, BATCH);         // (16, 16, 2)
    attn_mma_kernel<<<agrid, 256, ATTN_SMEM_BYTES>>>(gQ, gK, gV, gAO);

    // AO -> fp16 for the output projection, then out-proj
    convert_ao_kernel<<<(MTOT * DMODEL / 4) / 256, 256>>>(gAO, gAOh);
    dim3 ogrid(DMODEL / 128, MTOT / 128);        // (8, 32)
    gemm_out_kernel<<<ogrid, 256, GEMM_SMEM_BYTES>>>(gAOh,
                                                     gWt + 3 * (size_t)(DMODEL * DMODEL / 2),
                                                     bo, out);
}

// round 12
// speedup vs baseline: 1.9314x; 1.3242x over previous
#include <cuda_runtime.h>
#include <cuda_fp16.h>
#include <cstdint>

// Problem constants (fixed by the dataset)
#define BATCH    2
#define SEQ      2048
#define DMODEL   1024
#define NHEADS   16
#define HEADDIM  64
#define MTOT     (BATCH * SEQ)

// ---------------------------------------------------------------------------
// Scratch (__device__ globals) — all fp16 packed (2 halves per word)
// g_Q/g_K: [B,H,S,Hd/2] words (d-pairs packed)
// g_Vt:    [B,H,Hd,S/2] words (s-pairs packed; V transposed)
// g_AO:    [M, D/2] words
// g_Wt:    [N][K/2] words x4 ; g_Xt: [M][K/2] words
// ---------------------------------------------------------------------------
__device__ uint32_t g_Q [BATCH * NHEADS * SEQ * HEADDIM / 2];
__device__ uint32_t g_K [BATCH * NHEADS * SEQ * HEADDIM / 2];
__device__ uint32_t g_Vt[BATCH * NHEADS * HEADDIM * SEQ / 2];
__device__ uint32_t g_AO[MTOT * DMODEL / 2];
__device__ uint32_t g_Wt[4 * DMODEL * DMODEL / 2];
__device__ uint32_t g_Xt[MTOT * DMODEL / 2];

// ---------------------------------------------------------------------------
// Helpers
// ---------------------------------------------------------------------------
// fp16: D += A(16x16) @ B(16x8), fp32 accumulate
__device__ __forceinline__ void mma_f16_16x8x16(float c[4], const uint32_t a[4],
                                                const uint32_t b[2]) {
    asm volatile(
        "mma.sync.aligned.m16n8k16.row.col.f32.f16.f16.f32 "
        "{%0,%1,%2,%3}, {%4,%5,%6,%7}, {%8,%9}, {%0,%1,%2,%3};"
        : "+f"(c[0]), "+f"(c[1]), "+f"(c[2]), "+f"(c[3])
        : "r"(a[0]), "r"(a[1]), "r"(a[2]), "r"(a[3]), "r"(b[0]), "r"(b[1]));
}

__device__ __forceinline__ uint32_t smem_u32(const void* p) {
    uint32_t a;
    asm("{ .reg .u64 t; cvta.to.shared.u64 t, %1; cvt.u32.u64 %0, t; }" : "=r"(a) : "l"(p));
    return a;
}
__device__ __forceinline__ void cp_async16(uint32_t saddr, const void* gptr) {
    asm volatile("cp.async.ca.shared.global [%0], [%1], 16;" :: "r"(saddr), "l"(gptr));
}
__device__ __forceinline__ void cp_commit() {
    asm volatile("cp.async.commit_group;" ::: "memory");
}
template <int N> __device__ __forceinline__ void cp_wait() {
    asm volatile("cp.async.wait_group %0;" :: "n"(N) : "memory");
}
__device__ __forceinline__ uint32_t pack_h2(float a, float b) {
    __half2 h = __floats2half2_rn(a, b);
    return *(uint32_t*)&h;
}

// ---------------------------------------------------------------------------
// x -> fp16 convert (one pass)
// ---------------------------------------------------------------------------
__global__ void convert_x_kernel(const float* __restrict__ x)
{
    int idx = blockIdx.x * blockDim.x + threadIdx.x;     // float4 index
    float4 v = *(const float4*)(x + idx * 4);
    *(uint2*)(g_Xt + idx * 2) = make_uint2(pack_h2(v.x, v.y), pack_h2(v.z, v.w));
}

// ---------------------------------------------------------------------------
// Transpose + fp16 convert: Wt[n][k] = fp16(W[k][n]) for 4 weights
// ---------------------------------------------------------------------------
__global__ void transpose4_kernel(const float* __restrict__ W0, const float* __restrict__ W1,
                                  const float* __restrict__ W2, const float* __restrict__ W3)
{
    __shared__ float t[32][33];
    const float* src = (blockIdx.z == 0) ? W0 : (blockIdx.z == 1) ? W1
                     : (blockIdx.z == 2) ? W2 : W3;
    __half* dst = (__half*)(g_Wt + (size_t)blockIdx.z * (DMODEL * DMODEL / 2));

    int x = blockIdx.x * 32 + threadIdx.x;
    int y = blockIdx.y * 32 + threadIdx.y;
#pragma unroll
    for (int j = 0; j < 32; j += 8)
        t[threadIdx.y + j][threadIdx.x] = src[(size_t)(y + j) * DMODEL + x];
    __syncthreads();
    int x2 = blockIdx.y * 32 + threadIdx.x;
    int y2 = blockIdx.x * 32 + threadIdx.y;
#pragma unroll
    for (int j = 0; j < 32; j += 8)
        dst[(size_t)(y2 + j) * DMODEL + x2] = __float2half_rn(t[threadIdx.x][threadIdx.y + j]);
}

// ---------------------------------------------------------------------------
// fp16 GEMM mainloop (2-stage cp.async pipeline) — as validated in round 11
// ---------------------------------------------------------------------------
#define KWORDS 16
#define WPAD   20
#define TILEW  (128 * WPAD)
#define GEMM_SMEM_BYTES (4 * TILEW * 4)     // 40,960 B

#define GEMM_PROLOG \
    extern __shared__ uint32_t smw[]; \
    const uint32_t sbase = smem_u32(smw); \
    const int tid = threadIdx.x; \
    const int wid = tid >> 5, lane = tid & 31; \
    const int gid = lane >> 2, ctid = lane & 3; \
    const int warp_m = (wid & 3) * 32, warp_n = (wid >> 2) * 64; \
    const int n0 = blockIdx.x * 128, m0 = blockIdx.y * 128; \
    const int lrow = tid >> 1, lcw = (tid & 1) * 8;

#define GEMM_PREFETCH(st, kcw) do { \
    const uint32_t* Ab_ = A  + (size_t)(m0 + lrow) * (DMODEL / 2) + (kcw) + lcw; \
    const uint32_t* Bb_ = Bt + (size_t)(n0 + lrow) * (DMODEL / 2) + (kcw) + lcw; \
    uint32_t sa_ = sbase + ((st) * TILEW + lrow * WPAD + lcw) * 4; \
    uint32_t sb_ = sbase + ((2 + (st)) * TILEW + lrow * WPAD + lcw) * 4; \
    cp_async16(sa_,      Ab_);     \
    cp_async16(sa_ + 16, Ab_ + 4); \
    cp_async16(sb_,      Bb_);     \
    cp_async16(sb_ + 16, Bb_ + 4); \
    cp_commit(); \
} while (0)

#define GEMM_COMPUTE(st) do { \
    const uint32_t* Asw = smw + (st) * TILEW; \
    const uint32_t* Bsw = smw + (2 + (st)) * TILEW; \
    _Pragma("unroll") \
    for (int ks = 0; ks < 2; ks++) { \
        const int kb = ks * 8; \
        uint32_t afr[2][4]; \
        _Pragma("unroll") \
        for (int i = 0; i < 2; i++) { \
            const int r = warp_m + i * 16 + gid; \
            afr[i][0] = Asw[(r)     * WPAD + kb + ctid]; \
            afr[i][1] = Asw[(r + 8) * WPAD + kb + ctid]; \
            afr[i][2] = Asw[(r)     * WPAD + kb + ctid + 4]; \
            afr[i][3] = Asw[(r + 8) * WPAD + kb + ctid + 4]; \
        } \
        uint32_t bfr[8][2]; \
        _Pragma("unroll") \
        for (int j = 0; j < 8; j++) { \
            const int cn = warp_n + j * 8 + gid; \
            bfr[j][0] = Bsw[cn * WPAD + kb + ctid]; \
            bfr[j][1] = Bsw[cn * WPAD + kb + ctid + 4]; \
        } \
        _Pragma("unroll") \
        for (int i = 0; i < 2; i++) \
            _Pragma("unroll") \
            for (int j = 0; j < 8; j++) \
                mma_f16_16x8x16(acc[i][j], afr[i], bfr[j]); \
    } \
} while (0)

#define GEMM_MAINLOOP do { \
    GEMM_PREFETCH(0, 0); \
    for (int kc = 0; kc < 32; kc++) { \
        const int cur = kc & 1; \
        if (kc + 1 < 32) { GEMM_PREFETCH(cur ^ 1, (kc + 1) * KWORDS); cp_wait<1>(); } \
        else             { cp_wait<0>(); } \
        __syncthreads(); \
        GEMM_COMPUTE(cur); \
        __syncthreads(); \
    } \
} while (0)

// ---- QKV projection: grid (8, 32, 3)
//   z=0/1: Q/K packed fp16 [B,H,S,Hd/2]
//   z=2  : V transposed fp16 halves [B,H,Hd,S]
__global__ __launch_bounds__(256, 1)
void gemm_qkv_kernel(const uint32_t* __restrict__ A, const uint32_t* __restrict__ WtBase,
                     const float* __restrict__ bq, const float* __restrict__ bk,
                     const float* __restrict__ bv,
                     uint32_t* __restrict__ Qo, uint32_t* __restrict__ Ko,
                     uint32_t* __restrict__ Vto)
{
    GEMM_PROLOG
    const int z = blockIdx.z;
    const uint32_t* Bt = WtBase + (size_t)z * (DMODEL * DMODEL / 2);
    const float* bias = (z == 0) ? bq : (z == 1) ? bk : bv;

    float acc[2][8][4];
#pragma unroll
    for (int i = 0; i < 2; i++)
#pragma unroll
        for (int j = 0; j < 8; j++)
#pragma unroll
            for (int r = 0; r < 4; r++) acc[i][j][r] = 0.0f;

    GEMM_MAINLOOP;

#pragma unroll
    for (int i = 0; i < 2; i++) {
#pragma unroll
        for (int half = 0; half < 2; half++) {
            const int m = m0 + warp_m + i * 16 + gid + half * 8;
            const int b = m >> 11, s = m & 2047;
#pragma unroll
            for (int j = 0; j < 8; j++) {
                const int n = n0 + warp_n + j * 8 + ctid * 2;
                const int h = n >> 6, d0 = n & 63;
                const float v0 = acc[i][j][half * 2 + 0] + bias[n];
                const float v1 = acc[i][j][half * 2 + 1] + bias[n + 1];
                if (z < 2) {
                    uint32_t* C = (z == 0) ? Qo : Ko;
                    C[(((size_t)(b * NHEADS + h) * SEQ + s) << 5) + (d0 >> 1)] = pack_h2(v0, v1);
                } else {
                    __half* Vt = (__half*)Vto;
                    const size_t base = ((size_t)(b * NHEADS + h) * HEADDIM) << 11;  // *SEQ
                    Vt[base + (size_t)d0 * SEQ + s]       = __float2half_rn(v0);
                    Vt[base + (size_t)(d0 + 1) * SEQ + s] = __float2half_rn(v1);
                }
            }
        }
    }
}

// ---- Output projection: A fp16 packed (g_AO), row-major fp32 out ----
__global__ __launch_bounds__(256, 1)
void gemm_out_kernel(const uint32_t* __restrict__ A, const uint32_t* __restrict__ Bt,
                     const float* __restrict__ bias, float* __restrict__ C)
{
    GEMM_PROLOG

    float acc[2][8][4];
#pragma unroll
    for (int i = 0; i < 2; i++)
#pragma unroll
        for (int j = 0; j < 8; j++)
#pragma unroll
            for (int r = 0; r < 4; r++) acc[i][j][r] = 0.0f;

    GEMM_MAINLOOP;

#pragma unroll
    for (int i = 0; i < 2; i++) {
#pragma unroll
        for (int half = 0; half < 2; half++) {
            const int m = m0 + warp_m + i * 16 + gid + half * 8;
#pragma unroll
            for (int j = 0; j < 8; j++) {
                const int n = n0 + warp_n + j * 8 + ctid * 2;
                float* dst = C + (size_t)m * DMODEL + n;
                dst[0] = acc[i][j][half * 2 + 0] + bias[n];
                dst[1] = acc[i][j][half * 2 + 1] + bias[n + 1];
            }
        }
    }
}

// ---------------------------------------------------------------------------
// fp16 flash attention with ALiBi (mma.sync m16n8k16).
// Grid (16,16,2), 256 threads = 8 warps, warp owns 16 q-rows. 64-key chunks.
// Words = half2 pairs along k. All smem rows padded to 36 words:
// every load AND store phase hits addr ≡ 4*gid + ctid (mod 32) -> conflict-free.
// ---------------------------------------------------------------------------
#define AQ   128
#define AK   64
#define PWD  36     // padded row stride (words)

#define QH_OFF 0                           // 128*36 = 4608
#define KH_OFF (QH_OFF + AQ * PWD)         // 4608
#define VH_OFF (KH_OFF + AK * PWD)         // 6912
#define PH_OFF (VH_OFF + AK * PWD)         // 9216  (8 warps * 16 rows * 36)
#define ATTN_SMEM_WORDS (PH_OFF + 8 * 16 * PWD)   // 13824
#define ATTN_SMEM_BYTES (ATTN_SMEM_WORDS * 4)     // 55,296 B

__global__ __launch_bounds__(256, 2)
void attn_mma_kernel(const uint32_t* __restrict__ Q, const uint32_t* __restrict__ K,
                     const uint32_t* __restrict__ Vt, uint32_t* __restrict__ AO)
{
    extern __shared__ uint32_t smw[];
    uint32_t* Qh = smw + QH_OFF;
    uint32_t* Kh = smw + KH_OFF;
    uint32_t* Vh = smw + VH_OFF;
    uint32_t* Ph = smw + PH_OFF;

    const int tid  = threadIdx.x;
    const int wid  = tid >> 5;
    const int lane = tid & 31;
    const int gid  = lane >> 2;
    const int ctid = lane & 3;
    const int wrow = wid * 16;

    const int qt = blockIdx.x;
    const int h  = blockIdx.y;
    const int b  = blockIdx.z;
    const int q0 = qt * AQ;

    const uint32_t* Qb = Q  + (((size_t)(b * NHEADS + h) * SEQ + q0) << 5);
    const uint32_t* Kb = K  + (((size_t)(b * NHEADS + h) * SEQ) << 5);
    const uint32_t* Vb = Vt + (((size_t)(b * NHEADS + h) * HEADDIM) << 10);  // 1024 w/row

    // ---- load Q tile (128 rows x 32 words) ----
#pragma unroll
    for (int t = 0; t < 4; t++) {
        int idx = tid + t * 256;                 // uint4 idx 0..1023
        int row = idx >> 3;
        int w4  = (idx & 7) * 4;
        *(uint4*)&Qh[row * PWD + w4] = *(const uint4*)(Qb + row * 32 + w4);
    }

    const float slope = exp2f(-(float)h / (float)NHEADS);
    const float scale = 0.125f;
    const float qg0 = (float)(q0 + wrow + gid);
    const float qg1 = qg0 + 8.0f;

    float oacc[8][4];
#pragma unroll
    for (int j = 0; j < 8; j++)
#pragma unroll
        for (int r = 0; r < 4; r++) oacc[j][r] = 0.0f;
    float m0 = -1e30f, m1 = -1e30f, l0 = 0.0f, l1 = 0.0f;

    const int pr0 = PH_OFF - VH_OFF + 0;   // (unused guard; offsets applied below)

    for (int kt = 0; kt < SEQ; kt += AK) {
        __syncthreads();
        // ---- load K chunk (64x32 w) and Vt chunk (64 d-rows x 32 w) ----
#pragma unroll
        for (int t = 0; t < 2; t++) {
            int idx = tid + t * 256;             // uint4 idx 0..511
            int row = idx >> 3;
            int w4  = (idx & 7) * 4;
            *(uint4*)&Kh[row * PWD + w4] = *(const uint4*)(Kb + (size_t)(kt + row) * 32 + w4);
            *(uint4*)&Vh[row * PWD + w4] = *(const uint4*)(Vb + (size_t)row * 1024 + (kt >> 1) + w4);
        }
        __syncthreads();

        // ---- S = Q K^T : 4 k-steps of 16 (8 words) ----
        float sacc[8][4];
#pragma unroll
        for (int j = 0; j < 8; j++)
#pragma unroll
            for (int r = 0; r < 4; r++) sacc[j][r] = 0.0f;

#pragma unroll
        for (int ks = 0; ks < 4; ks++) {
            const int kb = ks * 8;
            uint32_t a[4];
            a[0] = Qh[(wrow + gid)     * PWD + kb + ctid];
            a[1] = Qh[(wrow + gid + 8) * PWD + kb + ctid];
            a[2] = Qh[(wrow + gid)     * PWD + kb + ctid + 4];
            a[3] = Qh[(wrow + gid + 8) * PWD + kb + ctid + 4];
#pragma unroll
            for (int nt = 0; nt < 8; nt++) {
                uint32_t bf[2];
                bf[0] = Kh[(nt * 8 + gid) * PWD + kb + ctid];
                bf[1] = Kh[(nt * 8 + gid) * PWD + kb + ctid + 4];
                mma_f16_16x8x16(sacc[nt], a, bf);
            }
        }

        // ---- ALiBi + scale + row max ----
        float mx0 = -1e30f, mx1 = -1e30f;
#pragma unroll
        for (int nt = 0; nt < 8; nt++) {
            const float kg = (float)(kt + nt * 8 + 2 * ctid);
            sacc[nt][0] = sacc[nt][0] * scale + slope * (kg        - qg0);
            sacc[nt][1] = sacc[nt][1] * scale + slope * (kg + 1.0f - qg0);
            sacc[nt][2] = sacc[nt][2] * scale + slope * (kg        - qg1);
            sacc[nt][3] = sacc[nt][3] * scale + slope * (kg + 1.0f - qg1);
            mx0 = fmaxf(mx0, fmaxf(sacc[nt][0], sacc[nt][1]));
            mx1 = fmaxf(mx1, fmaxf(sacc[nt][2], sacc[nt][3]));
        }
#pragma unroll
        for (int msk = 1; msk < 4; msk <<= 1) {
            mx0 = fmaxf(mx0, __shfl_xor_sync(0xffffffffu, mx0, msk));
            mx1 = fmaxf(mx1, __shfl_xor_sync(0xffffffffu, mx1, msk));
        }

        const float m0n = fmaxf(m0, mx0);
        const float m1n = fmaxf(m1, mx1);
        const float corr0 = __expf(m0 - m0n);
        const float corr1 = __expf(m1 - m1n);
        m0 = m0n; m1 = m1n;

        // ---- P = exp(S - m) -> warp-private Ph rows (fp16 pairs) ----
        float ps0 = 0.0f, ps1 = 0.0f;
        const int pb0 = (wrow + gid) * PWD;
        const int pb1 = (wrow + gid + 8) * PWD;
#pragma unroll
        for (int nt = 0; nt < 8; nt++) {
            float p0 = __expf(sacc[nt][0] - m0);
            float p1 = __expf(sacc[nt][1] - m0);
            float p2 = __expf(sacc[nt][2] - m1);
            float p3 = __expf(sacc[nt][3] - m1);
            ps0 += p0 + p1;
            ps1 += p2 + p3;
            Ph[pb0 + nt * 4 + ctid] = pack_h2(p0, p1);
            Ph[pb1 + nt * 4 + ctid] = pack_h2(p2, p3);
        }
#pragma unroll
        for (int msk = 1; msk < 4; msk <<= 1) {
            ps0 += __shfl_xor_sync(0xffffffffu, ps0, msk);
            ps1 += __shfl_xor_sync(0xffffffffu, ps1, msk);
        }
        l0 = l0 * corr0 + ps0;
        l1 = l1 * corr1 + ps1;

#pragma unroll
        for (int nt = 0; nt < 8; nt++) {
            oacc[nt][0] *= corr0; oacc[nt][1] *= corr0;
            oacc[nt][2] *= corr1; oacc[nt][3] *= corr1;
        }
        __syncwarp();   // Ph rows are warp-private

        // ---- O += P V : 4 k-steps of 16 keys (8 words) ----
#pragma unroll
        for (int ks = 0; ks < 4; ks++) {
            const int kb = ks * 8;
            uint32_t a[4];
            a[0] = Ph[pb0 + kb + ctid];
            a[1] = Ph[pb1 + kb + ctid];
            a[2] = Ph[pb0 + kb + ctid + 4];
            a[3] = Ph[pb1 + kb + ctid + 4];
#pragma unroll
            for (int nt = 0; nt < 8; nt++) {
                uint32_t bf[2];
                bf[0] = Vh[(nt * 8 + gid) * PWD + kb + ctid];
                bf[1] = Vh[(nt * 8 + gid) * PWD + kb + ctid + 4];
                mma_f16_16x8x16(oacc[nt], a, bf);
            }
        }
    }

    // ---- normalize, pack fp16, write AO [m][D/2 words] ----
    const float inv0 = 1.0f / l0;
    const float inv1 = 1.0f / l1;
    const int qr0 = q0 + wrow + gid;
    const int qr1 = qr0 + 8;
    uint32_t* dst0 = AO + (((size_t)(b * SEQ + qr0)) << 9) + h * 32;
    uint32_t* dst1 = AO + (((size_t)(b * SEQ + qr1)) << 9) + h * 32;
#pragma unroll
    for (int nt = 0; nt < 8; nt++) {
        dst0[nt * 4 + ctid] = pack_h2(oacc[nt][0] * inv0, oacc[nt][1] * inv0);
        dst1[nt * 4 + ctid] = pack_h2(oacc[nt][2] * inv1, oacc[nt][3] * inv1);
    }
}

// ---------------------------------------------------------------------------
// Launcher
// ---------------------------------------------------------------------------
extern "C" void kernel_launch(void* const* d_in, const int* in_sizes, int n_in,
                              void* d_out, int out_size)
{
    const float* x  = (const float*)d_in[0];
    const float* Wq = (const float*)d_in[1];
    const float* bq = (const float*)d_in[2];
    const float* Wk = (const float*)d_in[3];
    const float* bk = (const float*)d_in[4];
    const float* Wv = (const float*)d_in[5];
    const float* bv = (const float*)d_in[6];
    const float* Wo = (const float*)d_in[7];
    const float* bo = (const float*)d_in[8];
    float* out = (float*)d_out;

    uint32_t *gQ, *gK, *gVt, *gAO, *gWt, *gXt;
    cudaGetSymbolAddress((void**)&gQ,  g_Q);
    cudaGetSymbolAddress((void**)&gK,  g_K);
    cudaGetSymbolAddress((void**)&gVt, g_Vt);
    cudaGetSymbolAddress((void**)&gAO, g_AO);
    cudaGetSymbolAddress((void**)&gWt, g_Wt);
    cudaGetSymbolAddress((void**)&gXt, g_Xt);

    cudaFuncSetAttribute(gemm_qkv_kernel, cudaFuncAttributeMaxDynamicSharedMemorySize,
                         GEMM_SMEM_BYTES);
    cudaFuncSetAttribute(gemm_out_kernel, cudaFuncAttributeMaxDynamicSharedMemorySize,
                         GEMM_SMEM_BYTES);
    cudaFuncSetAttribute(attn_mma_kernel, cudaFuncAttributeMaxDynamicSharedMemorySize,
                         ATTN_SMEM_BYTES);

    // Prep: weight transpose+convert (fp16), x convert (fp16)
    transpose4_kernel<<<dim3(DMODEL / 32, DMODEL / 32, 4), dim3(32, 8)>>>(Wq, Wk, Wv, Wo);
    convert_x_kernel<<<(MTOT * DMODEL / 4) / 256, 256>>>(x);

    // QKV projections (one launch; z=2 writes V transposed)
    dim3 qkvgrid(DMODEL / 128, MTOT / 128, 3);   // (8, 32, 3)
    gemm_qkv_kernel<<<qkvgrid, 256, GEMM_SMEM_BYTES>>>(gXt, gWt, bq, bk, bv, gQ, gK, gVt);

    // Attention (fp16 m16n8k16)
    dim3 agrid(SEQ / AQ, NHEADS, BATCH);         // (16, 16, 2)
    attn_mma_kernel<<<agrid, 256, ATTN_SMEM_BYTES>>>(gQ, gK, gVt, gAO);

    // Output projection (A = fp16 AO)
    dim3 ogrid(DMODEL / 128, MTOT / 128);        // (8, 32)
    gemm_out_kernel<<<ogrid, 256, GEMM_SMEM_BYTES>>>(gAO,
                                                     gWt + 3 * (size_t)(DMODEL * DMODEL / 2),
                                                     bo, out);
}

// round 14
// speedup vs baseline: 2.1037x; 1.0892x over previous
#include <cuda_runtime.h>
#include <cuda_fp16.h>
#include <cstdint>

// Problem constants (fixed by the dataset)
#define BATCH    2
#define SEQ      2048
#define DMODEL   1024
#define NHEADS   16
#define HEADDIM  64
#define MTOT     (BATCH * SEQ)

#define LOG2E 1.44269504f

// ---------------------------------------------------------------------------
// Scratch (__device__ globals) — all fp16 packed (2 halves per word)
// g_Q: [B,H,S,Hd/2] (PRE-SCALED by 0.125*log2e) ; g_K: [B,H,S,Hd/2]
// g_Vt: [B,H,Hd,S/2] (V transposed) ; g_AO: [M,D/2]
// g_Wt: [N][K/2] x4 ; g_Xt: [M][K/2]
// ---------------------------------------------------------------------------
__device__ uint32_t g_Q [BATCH * NHEADS * SEQ * HEADDIM / 2];
__device__ uint32_t g_K [BATCH * NHEADS * SEQ * HEADDIM / 2];
__device__ uint32_t g_Vt[BATCH * NHEADS * HEADDIM * SEQ / 2];
__device__ uint32_t g_AO[MTOT * DMODEL / 2];
__device__ uint32_t g_Wt[4 * DMODEL * DMODEL / 2];
__device__ uint32_t g_Xt[MTOT * DMODEL / 2];

// ---------------------------------------------------------------------------
// Helpers
// ---------------------------------------------------------------------------
__device__ __forceinline__ void mma_f16_16x8x16(float c[4], const uint32_t a[4],
                                                const uint32_t b[2]) {
    asm volatile(
        "mma.sync.aligned.m16n8k16.row.col.f32.f16.f16.f32 "
        "{%0,%1,%2,%3}, {%4,%5,%6,%7}, {%8,%9}, {%0,%1,%2,%3};"
        : "+f"(c[0]), "+f"(c[1]), "+f"(c[2]), "+f"(c[3])
        : "r"(a[0]), "r"(a[1]), "r"(a[2]), "r"(a[3]), "r"(b[0]), "r"(b[1]));
}

__device__ __forceinline__ void ldsm_x4(uint32_t r[4], uint32_t addr) {
    asm volatile("ldmatrix.sync.aligned.m8n8.x4.shared.b16 {%0,%1,%2,%3}, [%4];"
        : "=r"(r[0]), "=r"(r[1]), "=r"(r[2]), "=r"(r[3]) : "r"(addr));
}

__device__ __forceinline__ uint32_t smem_u32(const void* p) {
    uint32_t a;
    asm("{ .reg .u64 t; cvta.to.shared.u64 t, %1; cvt.u32.u64 %0, t; }" : "=r"(a) : "l"(p));
    return a;
}
__device__ __forceinline__ void cp_async16(uint32_t saddr, const void* gptr) {
    asm volatile("cp.async.ca.shared.global [%0], [%1], 16;" :: "r"(saddr), "l"(gptr));
}
__device__ __forceinline__ void cp_commit() {
    asm volatile("cp.async.commit_group;" ::: "memory");
}
template <int N> __device__ __forceinline__ void cp_wait() {
    asm volatile("cp.async.wait_group %0;" :: "n"(N) : "memory");
}
__device__ __forceinline__ uint32_t pack_h2(float a, float b) {
    __half2 h = __floats2half2_rn(a, b);
    return *(uint32_t*)&h;
}

// ---------------------------------------------------------------------------
// x -> fp16 convert (one pass)
// ---------------------------------------------------------------------------
__global__ void convert_x_kernel(const float* __restrict__ x)
{
    int idx = blockIdx.x * blockDim.x + threadIdx.x;
    float4 v = *(const float4*)(x + idx * 4);
    *(uint2*)(g_Xt + idx * 2) = make_uint2(pack_h2(v.x, v.y), pack_h2(v.z, v.w));
}

// ---------------------------------------------------------------------------
// Transpose + fp16 convert: Wt[n][k] = fp16(W[k][n]) for 4 weights
// ---------------------------------------------------------------------------
__global__ void transpose4_kernel(const float* __restrict__ W0, const float* __restrict__ W1,
                                  const float* __restrict__ W2, const float* __restrict__ W3)
{
    __shared__ float t[32][33];
    const float* src = (blockIdx.z == 0) ? W0 : (blockIdx.z == 1) ? W1
                     : (blockIdx.z == 2) ? W2 : W3;
    __half* dst = (__half*)(g_Wt + (size_t)blockIdx.z * (DMODEL * DMODEL / 2));

    int x = blockIdx.x * 32 + threadIdx.x;
    int y = blockIdx.y * 32 + threadIdx.y;
#pragma unroll
    for (int j = 0; j < 32; j += 8)
        t[threadIdx.y + j][threadIdx.x] = src[(size_t)(y + j) * DMODEL + x];
    __syncthreads();
    int x2 = blockIdx.y * 32 + threadIdx.x;
    int y2 = blockIdx.x * 32 + threadIdx.y;
#pragma unroll
    for (int j = 0; j < 32; j += 8)
        dst[(size_t)(y2 + j) * DMODEL + x2] = __float2half_rn(t[threadIdx.x][threadIdx.y + j]);
}

// ---------------------------------------------------------------------------
// fp16 GEMM mainloop (2-stage cp.async pipeline) — validated rounds 11/12
// ---------------------------------------------------------------------------
#define KWORDS 16
#define WPAD   20
#define TILEW  (128 * WPAD)
#define GEMM_SMEM_BYTES (4 * TILEW * 4)     // 40,960 B

#define GEMM_PROLOG \
    extern __shared__ uint32_t smw[]; \
    const uint32_t sbase = smem_u32(smw); \
    const int tid = threadIdx.x; \
    const int wid = tid >> 5, lane = tid & 31; \
    const int gid = lane >> 2, ctid = lane & 3; \
    const int warp_m = (wid & 3) * 32, warp_n = (wid >> 2) * 64; \
    const int n0 = blockIdx.x * 128, m0 = blockIdx.y * 128; \
    const int lrow = tid >> 1, lcw = (tid & 1) * 8;

#define GEMM_PREFETCH(st, kcw) do { \
    const uint32_t* Ab_ = A  + (size_t)(m0 + lrow) * (DMODEL / 2) + (kcw) + lcw; \
    const uint32_t* Bb_ = Bt + (size_t)(n0 + lrow) * (DMODEL / 2) + (kcw) + lcw; \
    uint32_t sa_ = sbase + ((st) * TILEW + lrow * WPAD + lcw) * 4; \
    uint32_t sb_ = sbase + ((2 + (st)) * TILEW + lrow * WPAD + lcw) * 4; \
    cp_async16(sa_,      Ab_);     \
    cp_async16(sa_ + 16, Ab_ + 4); \
    cp_async16(sb_,      Bb_);     \
    cp_async16(sb_ + 16, Bb_ + 4); \
    cp_commit(); \
} while (0)

#define GEMM_COMPUTE(st) do { \
    const uint32_t* Asw = smw + (st) * TILEW; \
    const uint32_t* Bsw = smw + (2 + (st)) * TILEW; \
    _Pragma("unroll") \
    for (int ks = 0; ks < 2; ks++) { \
        const int kb = ks * 8; \
        uint32_t afr[2][4]; \
        _Pragma("unroll") \
        for (int i = 0; i < 2; i++) { \
            const int r = warp_m + i * 16 + gid; \
            afr[i][0] = Asw[(r)     * WPAD + kb + ctid]; \
            afr[i][1] = Asw[(r + 8) * WPAD + kb + ctid]; \
            afr[i][2] = Asw[(r)     * WPAD + kb + ctid + 4]; \
            afr[i][3] = Asw[(r + 8) * WPAD + kb + ctid + 4]; \
        } \
        uint32_t bfr[8][2]; \
        _Pragma("unroll") \
        for (int j = 0; j < 8; j++) { \
            const int cn = warp_n + j * 8 + gid; \
            bfr[j][0] = Bsw[cn * WPAD + kb + ctid]; \
            bfr[j][1] = Bsw[cn * WPAD + kb + ctid + 4]; \
        } \
        _Pragma("unroll") \
        for (int i = 0; i < 2; i++) \
            _Pragma("unroll") \
            for (int j = 0; j < 8; j++) \
                mma_f16_16x8x16(acc[i][j], afr[i], bfr[j]); \
    } \
} while (0)

#define GEMM_MAINLOOP do { \
    GEMM_PREFETCH(0, 0); \
    for (int kc = 0; kc < 32; kc++) { \
        const int cur = kc & 1; \
        if (kc + 1 < 32) { GEMM_PREFETCH(cur ^ 1, (kc + 1) * KWORDS); cp_wait<1>(); } \
        else             { cp_wait<0>(); } \
        __syncthreads(); \
        GEMM_COMPUTE(cur); \
        __syncthreads(); \
    } \
} while (0)

// ---- QKV projection: grid (8, 32, 3)
//   z=0: Q packed fp16, PRE-SCALED by 0.125*log2e ; z=1: K packed fp16
//   z=2: V transposed fp16 [B,H,Hd,S]
__global__ __launch_bounds__(256, 1)
void gemm_qkv_kernel(const uint32_t* __restrict__ A, const uint32_t* __restrict__ WtBase,
                     const float* __restrict__ bq, const float* __restrict__ bk,
                     const float* __restrict__ bv,
                     uint32_t* __restrict__ Qo, uint32_t* __restrict__ Ko,
                     uint32_t* __restrict__ Vto)
{
    GEMM_PROLOG
    const int z = blockIdx.z;
    const uint32_t* Bt = WtBase + (size_t)z * (DMODEL * DMODEL / 2);
    const float* bias = (z == 0) ? bq : (z == 1) ? bk : bv;
    const float oscale = (z == 0) ? (0.125f * LOG2E) : 1.0f;

    float acc[2][8][4];
#pragma unroll
    for (int i = 0; i < 2; i++)
#pragma unroll
        for (int j = 0; j < 8; j++)
#pragma unroll
            for (int r = 0; r < 4; r++) acc[i][j][r] = 0.0f;

    GEMM_MAINLOOP;

#pragma unroll
    for (int i = 0; i < 2; i++) {
#pragma unroll
        for (int half = 0; half < 2; half++) {
            const int m = m0 + warp_m + i * 16 + gid + half * 8;
            const int b = m >> 11, s = m & 2047;
#pragma unroll
            for (int j = 0; j < 8; j++) {
                const int n = n0 + warp_n + j * 8 + ctid * 2;
                const int h = n >> 6, d0 = n & 63;
                const float v0 = (acc[i][j][half * 2 + 0] + bias[n])     * oscale;
                const float v1 = (acc[i][j][half * 2 + 1] + bias[n + 1]) * oscale;
                if (z < 2) {
                    uint32_t* C = (z == 0) ? Qo : Ko;
                    C[(((size_t)(b * NHEADS + h) * SEQ + s) << 5) + (d0 >> 1)] = pack_h2(v0, v1);
                } else {
                    __half* Vt = (__half*)Vto;
                    const size_t base = ((size_t)(b * NHEADS + h) * HEADDIM) << 11;
                    Vt[base + (size_t)d0 * SEQ + s]       = __float2half_rn(v0);
                    Vt[base + (size_t)(d0 + 1) * SEQ + s] = __float2half_rn(v1);
                }
            }
        }
    }
}

// ---- Output projection: A fp16 packed (g_AO), row-major fp32 out ----
__global__ __launch_bounds__(256, 1)
void gemm_out_kernel(const uint32_t* __restrict__ A, const uint32_t* __restrict__ Bt,
                     const float* __restrict__ bias, float* __restrict__ C)
{
    GEMM_PROLOG

    float acc[2][8][4];
#pragma unroll
    for (int i = 0; i < 2; i++)
#pragma unroll
        for (int j = 0; j < 8; j++)
#pragma unroll
            for (int r = 0; r < 4; r++) acc[i][j][r] = 0.0f;

    GEMM_MAINLOOP;

#pragma unroll
    for (int i = 0; i < 2; i++) {
#pragma unroll
        for (int half = 0; half < 2; half++) {
            const int m = m0 + warp_m + i * 16 + gid + half * 8;
#pragma unroll
            for (int j = 0; j < 8; j++) {
                const int n = n0 + warp_n + j * 8 + ctid * 2;
                float* dst = C + (size_t)m * DMODEL + n;
                dst[0] = acc[i][j][half * 2 + 0] + bias[n];
                dst[1] = acc[i][j][half * 2 + 1] + bias[n + 1];
            }
        }
    }
}

// ---------------------------------------------------------------------------
// fp16 flash attention with ALiBi — ldmatrix fragments, cp.async K/V pipeline,
// log2-domain softmax (scale*log2e pre-folded into Q, -slope*q dropped:
// softmax-invariant; slope2*kt absorbed into the running max).
// Grid (16,16,2), 256 threads = 8 warps; warp owns 16 q-rows; 64-key chunks.
// ---------------------------------------------------------------------------
#define AQ   128
#define AK   64
#define PWD  36     // padded row stride (words); row stride 144 B -> ldmatrix c-free

#define QH_OFF 0                            // 128*36 = 4608
#define KH_OFF 4608                         // 2 stages x 64*36 = 2x2304
#define VH_OFF 9216                         // 2 stages x 2304
#define PH_OFF 13824                        // 128*36 = 4608
#define ATTN_SMEM_WORDS 18432
#define ATTN_SMEM_BYTES (ATTN_SMEM_WORDS * 4)   // 73,728 B

#define ATTN_PREFETCH(st, kt_) do { \
    _Pragma("unroll") \
    for (int t = 0; t < 2; t++) { \
        int idx = tid + t * 256; \
        int row = idx >> 3; \
        int w4  = (idx & 7) * 4; \
        cp_async16(sbase + (uint32_t)(KH_OFF + (st) * 2304 + row * PWD + w4) * 4, \
                   Kb + (size_t)((kt_) + row) * 32 + w4); \
        cp_async16(sbase + (uint32_t)(VH_OFF + (st) * 2304 + row * PWD + w4) * 4, \
                   Vb + (size_t)row * 1024 + ((kt_) >> 1) + w4); \
    } \
    cp_commit(); \
} while (0)

__global__ __launch_bounds__(256, 2)
void attn_mma_kernel(const uint32_t* __restrict__ Q, const uint32_t* __restrict__ K,
                     const uint32_t* __restrict__ Vt, uint32_t* __restrict__ AO)
{
    extern __shared__ uint32_t smw[];
    const uint32_t sbase = smem_u32(smw);
    uint32_t* Qh = smw + QH_OFF;
    uint32_t* Ph = smw + PH_OFF;

    const int tid  = threadIdx.x;
    const int wid  = tid >> 5;
    const int lane = tid & 31;
    const int gid  = lane >> 2;
    const int ctid = lane & 3;
    const int wrow = wid * 16;

    const int qt = blockIdx.x;
    const int h  = blockIdx.y;
    const int b  = blockIdx.z;
    const int q0 = qt * AQ;

    const uint32_t* Qb = Q  + (((size_t)(b * NHEADS + h) * SEQ + q0) << 5);
    const uint32_t* Kb = K  + (((size_t)(b * NHEADS + h) * SEQ) << 5);
    const uint32_t* Vb = Vt + (((size_t)(b * NHEADS + h) * HEADDIM) << 10);

    // ---- load Q tile (128 rows x 32 words) ----
#pragma unroll
    for (int t = 0; t < 4; t++) {
        int idx = tid + t * 256;
        int row = idx >> 3;
        int w4  = (idx & 7) * 4;
        *(uint4*)&Qh[row * PWD + w4] = *(const uint4*)(Qb + row * 32 + w4);
    }

    // ldmatrix lane addresses
    const int l15  = lane & 15;
    const int lhi  = lane >> 4;                 // 0/1 -> k-hi half
    const int brow = 8 * lhi + (lane & 7);      // B-pattern row within 16-row pair
    const int bko  = ((lane >> 3) & 1) * 4;     // B-pattern k word offset
    const uint32_t qA = sbase + (uint32_t)(QH_OFF + (wrow + l15) * PWD + lhi * 4) * 4;
    const uint32_t pA = sbase + (uint32_t)(PH_OFF + (wrow + l15) * PWD + lhi * 4) * 4;
    const uint32_t kB = sbase + (uint32_t)(KH_OFF + brow * PWD + bko) * 4;
    const uint32_t vB = sbase + (uint32_t)(VH_OFF + brow * PWD + bko) * 4;

    const float slope2 = exp2f(-(float)h / (float)NHEADS) * LOG2E;  // slope*log2e
    float bc0[8], bc1[8];                      // per-nt in-chunk ALiBi offsets
#pragma unroll
    for (int nt = 0; nt < 8; nt++) {
        bc0[nt] = slope2 * (float)(nt * 8 + 2 * ctid);
        bc1[nt] = bc0[nt] + slope2;
    }

    float oacc[8][4];
#pragma unroll
    for (int j = 0; j < 8; j++)
#pragma unroll
        for (int r = 0; r < 4; r++) oacc[j][r] = 0.0f;
    float m0 = -1e30f, m1 = -1e30f, l0 = 0.0f, l1 = 0.0f;

    ATTN_PREFETCH(0, 0);

    for (int c = 0; c < 32; c++) {
        const int kt = c * AK;
        const int cur = c & 1;
        if (c + 1 < 32) { ATTN_PREFETCH(cur ^ 1, kt + AK); cp_wait<1>(); }
        else            { cp_wait<0>(); }
        __syncthreads();

        const uint32_t kBs = kB + (uint32_t)(cur * 2304 * 4);
        const uint32_t vBs = vB + (uint32_t)(cur * 2304 * 4);

        // ---- S = Q K^T : 4 k-steps, ldmatrix fragments ----
        float sacc[8][4];
#pragma unroll
        for (int j = 0; j < 8; j++)
#pragma unroll
            for (int r = 0; r < 4; r++) sacc[j][r] = 0.0f;

#pragma unroll
        for (int ks = 0; ks < 4; ks++) {
            uint32_t a[4];
            ldsm_x4(a, qA + ks * 32);
#pragma unroll
            for (int p = 0; p < 4; p++) {            // nt pairs
                uint32_t bb[4];
                ldsm_x4(bb, kBs + (uint32_t)(p * 16 * PWD * 4) + ks * 32);
                mma_f16_16x8x16(sacc[2 * p],     a, bb);
                mma_f16_16x8x16(sacc[2 * p + 1], a, bb + 2);
            }
        }

        // ---- ALiBi (k-term only, log2 domain) + row max ----
        float e[8][4];
        float mx0 = -1e30f, mx1 = -1e30f;
#pragma unroll
        for (int nt = 0; nt < 8; nt++) {
            e[nt][0] = sacc[nt][0] + bc0[nt];
            e[nt][1] = sacc[nt][1] + bc1[nt];
            e[nt][2] = sacc[nt][2] + bc0[nt];
            e[nt][3] = sacc[nt][3] + bc1[nt];
            mx0 = fmaxf(mx0, fmaxf(e[nt][0], e[nt][1]));
            mx1 = fmaxf(mx1, fmaxf(e[nt][2], e[nt][3]));
        }
#pragma unroll
        for (int msk = 1; msk < 4; msk <<= 1) {
            mx0 = fmaxf(mx0, __shfl_xor_sync(0xffffffffu, mx0, msk));
            mx1 = fmaxf(mx1, __shfl_xor_sync(0xffffffffu, mx1, msk));
        }

        const float kbias = slope2 * (float)kt;      // chunk-global ALiBi shift
        const float m0n = fmaxf(m0, mx0 + kbias);
        const float m1n = fmaxf(m1, mx1 + kbias);
        const float corr0 = exp2f(m0 - m0n);
        const float corr1 = exp2f(m1 - m1n);
        m0 = m0n; m1 = m1n;
        const float mm0 = m0 - kbias;
        const float mm1 = m1 - kbias;

        // ---- P = exp2(e - mm) -> warp-private Ph rows (fp16 pairs) ----
        float ps0 = 0.0f, ps1 = 0.0f;
        const int pb0 = (wrow + gid) * PWD;
        const int pb1 = (wrow + gid + 8) * PWD;
#pragma unroll
        for (int nt = 0; nt < 8; nt++) {
            float p0 = exp2f(e[nt][0] - mm0);
            float p1 = exp2f(e[nt][1] - mm0);
            float p2 = exp2f(e[nt][2] - mm1);
            float p3 = exp2f(e[nt][3] - mm1);
            ps0 += p0 + p1;
            ps1 += p2 + p3;
            Ph[pb0 + nt * 4 + ctid] = pack_h2(p0, p1);
            Ph[pb1 + nt * 4 + ctid] = pack_h2(p2, p3);
        }
#pragma unroll
        for (int msk = 1; msk < 4; msk <<= 1) {
            ps0 += __shfl_xor_sync(0xffffffffu, ps0, msk);
            ps1 += __shfl_xor_sync(0xffffffffu, ps1, msk);
        }
        l0 = l0 * corr0 + ps0;
        l1 = l1 * corr1 + ps1;

#pragma unroll
        for (int nt = 0; nt < 8; nt++) {
            oacc[nt][0] *= corr0; oacc[nt][1] *= corr0;
            oacc[nt][2] *= corr1; oacc[nt][3] *= corr1;
        }
        __syncwarp();   // Ph rows are warp-private

        // ---- O += P V : ldmatrix fragments ----
#pragma unroll
        for (int ks = 0; ks < 4; ks++) {
            uint32_t a[4];
            ldsm_x4(a, pA + ks * 32);
#pragma unroll
            for (int p = 0; p < 4; p++) {
                uint32_t bb[4];
                ldsm_x4(bb, vBs + (uint32_t)(p * 16 * PWD * 4) + ks * 32);
                mma_f16_16x8x16(oacc[2 * p],     a, bb);
                mma_f16_16x8x16(oacc[2 * p + 1], a, bb + 2);
            }
        }
        __syncthreads();   // done reading stage cur before it is refilled
    }

    // ---- normalize, pack fp16, write AO [m][D/2 words] ----
    const float inv0 = 1.0f / l0;
    const float inv1 = 1.0f / l1;
    const int qr0 = q0 + wrow + gid;
    const int qr1 = qr0 + 8;
    uint32_t* dst0 = AO + (((size_t)(b * SEQ + qr0)) << 9) + h * 32;
    uint32_t* dst1 = AO + (((size_t)(b * SEQ + qr1)) << 9) + h * 32;
#pragma unroll
    for (int nt = 0; nt < 8; nt++) {
        dst0[nt * 4 + ctid] = pack_h2(oacc[nt][0] * inv0, oacc[nt][1] * inv0);
        dst1[nt * 4 + ctid] = pack_h2(oacc[nt][2] * inv1, oacc[nt][3] * inv1);
    }
}

// ---------------------------------------------------------------------------
// Launcher
// ---------------------------------------------------------------------------
extern "C" void kernel_launch(void* const* d_in, const int* in_sizes, int n_in,
                              void* d_out, int out_size)
{
    const float* x  = (const float*)d_in[0];
    const float* Wq = (const float*)d_in[1];
    const float* bq = (const float*)d_in[2];
    const float* Wk = (const float*)d_in[3];
    const float* bk = (const float*)d_in[4];
    const float* Wv = (const float*)d_in[5];
    const float* bv = (const float*)d_in[6];
    const float* Wo = (const float*)d_in[7];
    const float* bo = (const float*)d_in[8];
    float* out = (float*)d_out;

    uint32_t *gQ, *gK, *gVt, *gAO, *gWt, *gXt;
    cudaGetSymbolAddress((void**)&gQ,  g_Q);
    cudaGetSymbolAddress((void**)&gK,  g_K);
    cudaGetSymbolAddress((void**)&gVt, g_Vt);
    cudaGetSymbolAddress((void**)&gAO, g_AO);
    cudaGetSymbolAddress((void**)&gWt, g_Wt);
    cudaGetSymbolAddress((void**)&gXt, g_Xt);

    cudaFuncSetAttribute(gemm_qkv_kernel, cudaFuncAttributeMaxDynamicSharedMemorySize,
                         GEMM_SMEM_BYTES);
    cudaFuncSetAttribute(gemm_out_kernel, cudaFuncAttributeMaxDynamicSharedMemorySize,
                         GEMM_SMEM_BYTES);
    cudaFuncSetAttribute(attn_mma_kernel, cudaFuncAttributeMaxDynamicSharedMemorySize,
                         ATTN_SMEM_BYTES);

    // Prep: weight transpose+convert (fp16), x convert (fp16)
    transpose4_kernel<<<dim3(DMODEL / 32, DMODEL / 32, 4), dim3(32, 8)>>>(Wq, Wk, Wv, Wo);
    convert_x_kernel<<<(MTOT * DMODEL / 4) / 256, 256>>>(x);

    // QKV projections (one launch; z=0 pre-scales Q; z=2 writes V transposed)
    dim3 qkvgrid(DMODEL / 128, MTOT / 128, 3);   // (8, 32, 3)
    gemm_qkv_kernel<<<qkvgrid, 256, GEMM_SMEM_BYTES>>>(gXt, gWt, bq, bk, bv, gQ, gK, gVt);

    // Attention (fp16, ldmatrix + cp.async + log2-domain softmax)
    dim3 agrid(SEQ / AQ, NHEADS, BATCH);         // (16, 16, 2)
    attn_mma_kernel<<<agrid, 256, ATTN_SMEM_BYTES>>>(gQ, gK, gVt, gAO);

    // Output projection (A = fp16 AO)
    dim3 ogrid(DMODEL / 128, MTOT / 128);        // (8, 32)
    gemm_out_kernel<<<ogrid, 256, GEMM_SMEM_BYTES>>>(gAO,
                                                     gWt + 3 * (size_t)(DMODEL * DMODEL / 2),
                                                     bo, out);
}

// round 16
// speedup vs baseline: 2.2831x; 1.0853x over previous
#include <cuda_runtime.h>
#include <cuda_fp16.h>
#include <cstdint>

// Problem constants (fixed by the dataset)
#define BATCH    2
#define SEQ      2048
#define DMODEL   1024
#define NHEADS   16
#define HEADDIM  64
#define MTOT     (BATCH * SEQ)

#define LOG2E 1.44269504f

// ---------------------------------------------------------------------------
// Scratch (__device__ globals) — all fp16 packed (2 halves per word)
// ---------------------------------------------------------------------------
__device__ uint32_t g_Q [BATCH * NHEADS * SEQ * HEADDIM / 2];
__device__ uint32_t g_K [BATCH * NHEADS * SEQ * HEADDIM / 2];
__device__ uint32_t g_Vt[BATCH * NHEADS * HEADDIM * SEQ / 2];
__device__ uint32_t g_AO[MTOT * DMODEL / 2];
__device__ uint32_t g_Wt[4 * DMODEL * DMODEL / 2];
__device__ uint32_t g_Xt[MTOT * DMODEL / 2];

// ---------------------------------------------------------------------------
// Helpers
// ---------------------------------------------------------------------------
__device__ __forceinline__ void mma_f16_16x8x16(float c[4], const uint32_t a[4],
                                                const uint32_t b[2]) {
    asm volatile(
        "mma.sync.aligned.m16n8k16.row.col.f32.f16.f16.f32 "
        "{%0,%1,%2,%3}, {%4,%5,%6,%7}, {%8,%9}, {%0,%1,%2,%3};"
        : "+f"(c[0]), "+f"(c[1]), "+f"(c[2]), "+f"(c[3])
        : "r"(a[0]), "r"(a[1]), "r"(a[2]), "r"(a[3]), "r"(b[0]), "r"(b[1]));
}

__device__ __forceinline__ void ldsm_x4(uint32_t r[4], uint32_t addr) {
    asm volatile("ldmatrix.sync.aligned.m8n8.x4.shared.b16 {%0,%1,%2,%3}, [%4];"
        : "=r"(r[0]), "=r"(r[1]), "=r"(r[2]), "=r"(r[3]) : "r"(addr));
}

__device__ __forceinline__ uint32_t smem_u32(const void* p) {
    uint32_t a;
    asm("{ .reg .u64 t; cvta.to.shared.u64 t, %1; cvt.u32.u64 %0, t; }" : "=r"(a) : "l"(p));
    return a;
}
__device__ __forceinline__ void cp_async16(uint32_t saddr, const void* gptr) {
    asm volatile("cp.async.ca.shared.global [%0], [%1], 16;" :: "r"(saddr), "l"(gptr));
}
__device__ __forceinline__ void cp_commit() {
    asm volatile("cp.async.commit_group;" ::: "memory");
}
template <int N> __device__ __forceinline__ void cp_wait() {
    asm volatile("cp.async.wait_group %0;" :: "n"(N) : "memory");
}
__device__ __forceinline__ uint32_t pack_h2(float a, float b) {
    __half2 h = __floats2half2_rn(a, b);
    return *(uint32_t*)&h;
}

// ---------------------------------------------------------------------------
// x -> fp16 convert (one pass)
// ---------------------------------------------------------------------------
__global__ void convert_x_kernel(const float* __restrict__ x)
{
    int idx = blockIdx.x * blockDim.x + threadIdx.x;
    float4 v = *(const float4*)(x + idx * 4);
    *(uint2*)(g_Xt + idx * 2) = make_uint2(pack_h2(v.x, v.y), pack_h2(v.z, v.w));
}

// ---------------------------------------------------------------------------
// Transpose + fp16 convert: Wt[n][k] = fp16(W[k][n]) for 4 weights
// ---------------------------------------------------------------------------
__global__ void transpose4_kernel(const float* __restrict__ W0, const float* __restrict__ W1,
                                  const float* __restrict__ W2, const float* __restrict__ W3)
{
    __shared__ float t[32][33];
    const float* src = (blockIdx.z == 0) ? W0 : (blockIdx.z == 1) ? W1
                     : (blockIdx.z == 2) ? W2 : W3;
    __half* dst = (__half*)(g_Wt + (size_t)blockIdx.z * (DMODEL * DMODEL / 2));

    int x = blockIdx.x * 32 + threadIdx.x;
    int y = blockIdx.y * 32 + threadIdx.y;
#pragma unroll
    for (int j = 0; j < 32; j += 8)
        t[threadIdx.y + j][threadIdx.x] = src[(size_t)(y + j) * DMODEL + x];
    __syncthreads();
    int x2 = blockIdx.y * 32 + threadIdx.x;
    int y2 = blockIdx.x * 32 + threadIdx.y;
#pragma unroll
    for (int j = 0; j < 32; j += 8)
        dst[(size_t)(y2 + j) * DMODEL + x2] = __float2half_rn(t[threadIdx.x][threadIdx.y + j]);
}

// ---------------------------------------------------------------------------
// fp16 GEMM mainloop (2-stage cp.async pipeline, ldmatrix fragments)
// CTA 128x128, 256 threads = 8 warps (4M x 2N), warp tile 32x64.
// WPAD=20: ldsm phase rows r..r+7 -> bank-groups r*5 mod 8 distinct (c-free).
// ---------------------------------------------------------------------------
#define KWORDS 16
#define WPAD   20
#define TILEW  (128 * WPAD)
#define GEMM_SMEM_BYTES (4 * TILEW * 4)     // 40,960 B

#define GEMM_PROLOG \
    extern __shared__ uint32_t smw[]; \
    const uint32_t sbase = smem_u32(smw); \
    const int tid = threadIdx.x; \
    const int wid = tid >> 5, lane = tid & 31; \
    const int gid = lane >> 2, ctid = lane & 3; \
    const int warp_m = (wid & 3) * 32, warp_n = (wid >> 2) * 64; \
    const int n0 = blockIdx.x * 128, m0 = blockIdx.y * 128; \
    const int lrow = tid >> 1, lcw = (tid & 1) * 8; \
    const int l15 = lane & 15, lhi = lane >> 4; \
    const int brow = 8 * lhi + (lane & 7), bko = ((lane >> 3) & 1) * 4;

#define GEMM_PREFETCH(st, kcw) do { \
    const uint32_t* Ab_ = A  + (size_t)(m0 + lrow) * (DMODEL / 2) + (kcw) + lcw; \
    const uint32_t* Bb_ = Bt + (size_t)(n0 + lrow) * (DMODEL / 2) + (kcw) + lcw; \
    uint32_t sa_ = sbase + ((st) * TILEW + lrow * WPAD + lcw) * 4; \
    uint32_t sb_ = sbase + ((2 + (st)) * TILEW + lrow * WPAD + lcw) * 4; \
    cp_async16(sa_,      Ab_);     \
    cp_async16(sa_ + 16, Ab_ + 4); \
    cp_async16(sb_,      Bb_);     \
    cp_async16(sb_ + 16, Bb_ + 4); \
    cp_commit(); \
} while (0)

#define GEMM_COMPUTE(st) do { \
    const uint32_t abase_ = sbase + ((st) * TILEW) * 4; \
    const uint32_t bbase_ = sbase + ((2 + (st)) * TILEW) * 4; \
    _Pragma("unroll") \
    for (int ks = 0; ks < 2; ks++) { \
        const int kb = ks * 8; \
        uint32_t afr[2][4]; \
        ldsm_x4(afr[0], abase_ + (uint32_t)((warp_m      + l15) * WPAD + kb + lhi * 4) * 4); \
        ldsm_x4(afr[1], abase_ + (uint32_t)((warp_m + 16 + l15) * WPAD + kb + lhi * 4) * 4); \
        uint32_t bfr[4][4]; \
        _Pragma("unroll") \
        for (int p = 0; p < 4; p++) \
            ldsm_x4(bfr[p], bbase_ + (uint32_t)((warp_n + p * 16 + brow) * WPAD + kb + bko) * 4); \
        _Pragma("unroll") \
        for (int i = 0; i < 2; i++) \
            _Pragma("unroll") \
            for (int p = 0; p < 4; p++) { \
                mma_f16_16x8x16(acc[i][2 * p],     afr[i], bfr[p]); \
                mma_f16_16x8x16(acc[i][2 * p + 1], afr[i], bfr[p] + 2); \
            } \
    } \
} while (0)

#define GEMM_MAINLOOP do { \
    GEMM_PREFETCH(0, 0); \
    for (int kc = 0; kc < 32; kc++) { \
        const int cur = kc & 1; \
        if (kc + 1 < 32) { GEMM_PREFETCH(cur ^ 1, (kc + 1) * KWORDS); cp_wait<1>(); } \
        else             { cp_wait<0>(); } \
        __syncthreads(); \
        GEMM_COMPUTE(cur); \
        __syncthreads(); \
    } \
} while (0)

// ---- QKV projection: grid (8, 32, 3)
//   z=0: Q packed fp16, PRE-SCALED by 0.125*log2e ; z=1: K packed fp16
//   z=2: V transposed fp16 [B,H,Hd,S]
__global__ __launch_bounds__(256, 1)
void gemm_qkv_kernel(const uint32_t* __restrict__ A, const uint32_t* __restrict__ WtBase,
                     const float* __restrict__ bq, const float* __restrict__ bk,
                     const float* __restrict__ bv,
                     uint32_t* __restrict__ Qo, uint32_t* __restrict__ Ko,
                     uint32_t* __restrict__ Vto)
{
    GEMM_PROLOG
    const int z = blockIdx.z;
    const uint32_t* Bt = WtBase + (size_t)z * (DMODEL * DMODEL / 2);
    const float* bias = (z == 0) ? bq : (z == 1) ? bk : bv;
    const float oscale = (z == 0) ? (0.125f * LOG2E) : 1.0f;

    float acc[2][8][4];
#pragma unroll
    for (int i = 0; i < 2; i++)
#pragma unroll
        for (int j = 0; j < 8; j++)
#pragma unroll
            for (int r = 0; r < 4; r++) acc[i][j][r] = 0.0f;

    GEMM_MAINLOOP;

#pragma unroll
    for (int i = 0; i < 2; i++) {
#pragma unroll
        for (int half = 0; half < 2; half++) {
            const int m = m0 + warp_m + i * 16 + gid + half * 8;
            const int b = m >> 11, s = m & 2047;
#pragma unroll
            for (int j = 0; j < 8; j++) {
                const int n = n0 + warp_n + j * 8 + ctid * 2;
                const int h = n >> 6, d0 = n & 63;
                const float v0 = (acc[i][j][half * 2 + 0] + bias[n])     * oscale;
                const float v1 = (acc[i][j][half * 2 + 1] + bias[n + 1]) * oscale;
                if (z < 2) {
                    uint32_t* C = (z == 0) ? Qo : Ko;
                    C[(((size_t)(b * NHEADS + h) * SEQ + s) << 5) + (d0 >> 1)] = pack_h2(v0, v1);
                } else {
                    __half* Vt = (__half*)Vto;
                    const size_t base = ((size_t)(b * NHEADS + h) * HEADDIM) << 11;
                    Vt[base + (size_t)d0 * SEQ + s]       = __float2half_rn(v0);
                    Vt[base + (size_t)(d0 + 1) * SEQ + s] = __float2half_rn(v1);
                }
            }
        }
    }
}

// ---- Output projection: A fp16 packed (g_AO), row-major fp32 out ----
__global__ __launch_bounds__(256, 1)
void gemm_out_kernel(const uint32_t* __restrict__ A, const uint32_t* __restrict__ Bt,
                     const float* __restrict__ bias, float* __restrict__ C)
{
    GEMM_PROLOG

    float acc[2][8][4];
#pragma unroll
    for (int i = 0; i < 2; i++)
#pragma unroll
        for (int j = 0; j < 8; j++)
#pragma unroll
            for (int r = 0; r < 4; r++) acc[i][j][r] = 0.0f;

    GEMM_MAINLOOP;

#pragma unroll
    for (int i = 0; i < 2; i++) {
#pragma unroll
        for (int half = 0; half < 2; half++) {
            const int m = m0 + warp_m + i * 16 + gid + half * 8;
#pragma unroll
            for (int j = 0; j < 8; j++) {
                const int n = n0 + warp_n + j * 8 + ctid * 2;
                float* dst = C + (size_t)m * DMODEL + n;
                dst[0] = acc[i][j][half * 2 + 0] + bias[n];
                dst[1] = acc[i][j][half * 2 + 1] + bias[n + 1];
            }
        }
    }
}

// ---------------------------------------------------------------------------
// fp16 flash attention with ALiBi — register-resident P (the S C-fragment
// layout equals the PV A-fragment layout), hoisted Q fragments, ldmatrix K/V,
// cp.async double-buffered K/V, log2-domain softmax.
// Grid (16,16,2), 256 threads = 8 warps; warp owns 16 q-rows; 64-key chunks.
// ---------------------------------------------------------------------------
#define AQ   128
#define AK   64
#define PWD  36     // padded row stride (words)

#define QH_OFF 0                            // 128*36 = 4608
#define KH_OFF 4608                         // 2 stages x 64*36 = 2x2304
#define VH_OFF 9216                         // 2 stages x 2304
#define ATTN_SMEM_WORDS 13824
#define ATTN_SMEM_BYTES (ATTN_SMEM_WORDS * 4)   // 55,296 B

#define ATTN_PREFETCH(st, kt_) do { \
    _Pragma("unroll") \
    for (int t = 0; t < 2; t++) { \
        int idx = tid + t * 256; \
        int row = idx >> 3; \
        int w4  = (idx & 7) * 4; \
        cp_async16(sbase + (uint32_t)(KH_OFF + (st) * 2304 + row * PWD + w4) * 4, \
                   Kb + (size_t)((kt_) + row) * 32 + w4); \
        cp_async16(sbase + (uint32_t)(VH_OFF + (st) * 2304 + row * PWD + w4) * 4, \
                   Vb + (size_t)row * 1024 + ((kt_) >> 1) + w4); \
    } \
    cp_commit(); \
} while (0)

__global__ __launch_bounds__(256, 2)
void attn_mma_kernel(const uint32_t* __restrict__ Q, const uint32_t* __restrict__ K,
                     const uint32_t* __restrict__ Vt, uint32_t* __restrict__ AO)
{
    extern __shared__ uint32_t smw[];
    const uint32_t sbase = smem_u32(smw);
    uint32_t* Qh = smw + QH_OFF;

    const int tid  = threadIdx.x;
    const int wid  = tid >> 5;
    const int lane = tid & 31;
    const int gid  = lane >> 2;
    const int ctid = lane & 3;
    const int wrow = wid * 16;

    const int qt = blockIdx.x;
    const int h  = blockIdx.y;
    const int b  = blockIdx.z;
    const int q0 = qt * AQ;

    const uint32_t* Qb = Q  + (((size_t)(b * NHEADS + h) * SEQ + q0) << 5);
    const uint32_t* Kb = K  + (((size_t)(b * NHEADS + h) * SEQ) << 5);
    const uint32_t* Vb = Vt + (((size_t)(b * NHEADS + h) * HEADDIM) << 10);

    // ---- load Q tile (128 rows x 32 words) ----
#pragma unroll
    for (int t = 0; t < 4; t++) {
        int idx = tid + t * 256;
        int row = idx >> 3;
        int w4  = (idx & 7) * 4;
        *(uint4*)&Qh[row * PWD + w4] = *(const uint4*)(Qb + row * 32 + w4);
    }

    // ldmatrix lane addresses
    const int l15  = lane & 15;
    const int lhi  = lane >> 4;
    const int brow = 8 * lhi + (lane & 7);
    const int bko  = ((lane >> 3) & 1) * 4;
    const uint32_t qA = sbase + (uint32_t)(QH_OFF + (wrow + l15) * PWD + lhi * 4) * 4;
    const uint32_t kB = sbase + (uint32_t)(KH_OFF + brow * PWD + bko) * 4;
    const uint32_t vB = sbase + (uint32_t)(VH_OFF + brow * PWD + bko) * 4;

    __syncthreads();
    // ---- hoist Q fragments into registers (whole kernel) ----
    uint32_t qfrag[4][4];
#pragma unroll
    for (int ks = 0; ks < 4; ks++)
        ldsm_x4(qfrag[ks], qA + ks * 32);

    const float slope2 = exp2f(-(float)h / (float)NHEADS) * LOG2E;
    float bc0[8], bc1[8];
#pragma unroll
    for (int nt = 0; nt < 8; nt++) {
        bc0[nt] = slope2 * (float)(nt * 8 + 2 * ctid);
        bc1[nt] = bc0[nt] + slope2;
    }

    float oacc[8][4];
#pragma unroll
    for (int j = 0; j < 8; j++)
#pragma unroll
        for (int r = 0; r < 4; r++) oacc[j][r] = 0.0f;
    float m0 = -1e30f, m1 = -1e30f, l0 = 0.0f, l1 = 0.0f;

    ATTN_PREFETCH(0, 0);

    for (int c = 0; c < 32; c++) {
        const int kt = c * AK;
        const int cur = c & 1;
        if (c + 1 < 32) { ATTN_PREFETCH(cur ^ 1, kt + AK); cp_wait<1>(); }
        else            { cp_wait<0>(); }
        __syncthreads();

        const uint32_t kBs = kB + (uint32_t)(cur * 2304 * 4);
        const uint32_t vBs = vB + (uint32_t)(cur * 2304 * 4);

        // ---- S = Q K^T ----
        float sacc[8][4];
#pragma unroll
        for (int j = 0; j < 8; j++)
#pragma unroll
            for (int r = 0; r < 4; r++) sacc[j][r] = 0.0f;

#pragma unroll
        for (int ks = 0; ks < 4; ks++) {
#pragma unroll
            for (int p = 0; p < 4; p++) {
                uint32_t bb[4];
                ldsm_x4(bb, kBs + (uint32_t)(p * 16 * PWD * 4) + ks * 32);
                mma_f16_16x8x16(sacc[2 * p],     qfrag[ks], bb);
                mma_f16_16x8x16(sacc[2 * p + 1], qfrag[ks], bb + 2);
            }
        }

        // ---- ALiBi (k-term, log2 domain) in place + row max ----
        float mx0 = -1e30f, mx1 = -1e30f;
#pragma unroll
        for (int nt = 0; nt < 8; nt++) {
            sacc[nt][0] += bc0[nt];
            sacc[nt][1] += bc1[nt];
            sacc[nt][2] += bc0[nt];
            sacc[nt][3] += bc1[nt];
            mx0 = fmaxf(mx0, fmaxf(sacc[nt][0], sacc[nt][1]));
            mx1 = fmaxf(mx1, fmaxf(sacc[nt][2], sacc[nt][3]));
        }
#pragma unroll
        for (int msk = 1; msk < 4; msk <<= 1) {
            mx0 = fmaxf(mx0, __shfl_xor_sync(0xffffffffu, mx0, msk));
            mx1 = fmaxf(mx1, __shfl_xor_sync(0xffffffffu, mx1, msk));
        }

        const float kbias = slope2 * (float)kt;
        const float m0n = fmaxf(m0, mx0 + kbias);
        const float m1n = fmaxf(m1, mx1 + kbias);
        const float corr0 = exp2f(m0 - m0n);
        const float corr1 = exp2f(m1 - m1n);
        m0 = m0n; m1 = m1n;
        const float mm0 = m0 - kbias;
        const float mm1 = m1 - kbias;

        // ---- P = exp2(sacc - mm) packed DIRECTLY into PV A-fragments ----
        // pf[nt][0] = (row gid, keys nt*8+2ctid..+1); pf[nt][1] = (row gid+8, same)
        uint32_t pf[8][2];
        float ps0 = 0.0f, ps1 = 0.0f;
#pragma unroll
        for (int nt = 0; nt < 8; nt++) {
            float p0 = exp2f(sacc[nt][0] - mm0);
            float p1 = exp2f(sacc[nt][1] - mm0);
            float p2 = exp2f(sacc[nt][2] - mm1);
            float p3 = exp2f(sacc[nt][3] - mm1);
            ps0 += p0 + p1;
            ps1 += p2 + p3;
            pf[nt][0] = pack_h2(p0, p1);
            pf[nt][1] = pack_h2(p2, p3);
        }
#pragma unroll
        for (int msk = 1; msk < 4; msk <<= 1) {
            ps0 += __shfl_xor_sync(0xffffffffu, ps0, msk);
            ps1 += __shfl_xor_sync(0xffffffffu, ps1, msk);
        }
        l0 = l0 * corr0 + ps0;
        l1 = l1 * corr1 + ps1;

#pragma unroll
        for (int nt = 0; nt < 8; nt++) {
            oacc[nt][0] *= corr0; oacc[nt][1] *= corr0;
            oacc[nt][2] *= corr1; oacc[nt][3] *= corr1;
        }

        // ---- O += P V : A from registers (pf), B via ldmatrix ----
#pragma unroll
        for (int ks = 0; ks < 4; ks++) {
            uint32_t a[4];
            a[0] = pf[2 * ks][0];
            a[1] = pf[2 * ks][1];
            a[2] = pf[2 * ks + 1][0];
            a[3] = pf[2 * ks + 1][1];
#pragma unroll
            for (int p = 0; p < 4; p++) {
                uint32_t bb[4];
                ldsm_x4(bb, vBs + (uint32_t)(p * 16 * PWD * 4) + ks * 32);
                mma_f16_16x8x16(oacc[2 * p],     a, bb);
                mma_f16_16x8x16(oacc[2 * p + 1], a, bb + 2);
            }
        }
        __syncthreads();   // done reading stage cur before it is refilled
    }

    // ---- normalize, pack fp16, write AO [m][D/2 words] ----
    const float inv0 = 1.0f / l0;
    const float inv1 = 1.0f / l1;
    const int qr0 = q0 + wrow + gid;
    const int qr1 = qr0 + 8;
    uint32_t* dst0 = AO + (((size_t)(b * SEQ + qr0)) << 9) + h * 32;
    uint32_t* dst1 = AO + (((size_t)(b * SEQ + qr1)) << 9) + h * 32;
#pragma unroll
    for (int nt = 0; nt < 8; nt++) {
        dst0[nt * 4 + ctid] = pack_h2(oacc[nt][0] * inv0, oacc[nt][1] * inv0);
        dst1[nt * 4 + ctid] = pack_h2(oacc[nt][2] * inv1, oacc[nt][3] * inv1);
    }
}

// ---------------------------------------------------------------------------
// Launcher
// ---------------------------------------------------------------------------
extern "C" void kernel_launch(void* const* d_in, const int* in_sizes, int n_in,
                              void* d_out, int out_size)
{
    const float* x  = (const float*)d_in[0];
    const float* Wq = (const float*)d_in[1];
    const float* bq = (const float*)d_in[2];
    const float* Wk = (const float*)d_in[3];
    const float* bk = (const float*)d_in[4];
    const float* Wv = (const float*)d_in[5];
    const float* bv = (const float*)d_in[6];
    const float* Wo = (const float*)d_in[7];
    const float* bo = (const float*)d_in[8];
    float* out = (float*)d_out;

    uint32_t *gQ, *gK, *gVt, *gAO, *gWt, *gXt;
    cudaGetSymbolAddress((void**)&gQ,  g_Q);
    cudaGetSymbolAddress((void**)&gK,  g_K);
    cudaGetSymbolAddress((void**)&gVt, g_Vt);
    cudaGetSymbolAddress((void**)&gAO, g_AO);
    cudaGetSymbolAddress((void**)&gWt, g_Wt);
    cudaGetSymbolAddress((void**)&gXt, g_Xt);

    cudaFuncSetAttribute(gemm_qkv_kernel, cudaFuncAttributeMaxDynamicSharedMemorySize,
                         GEMM_SMEM_BYTES);
    cudaFuncSetAttribute(gemm_out_kernel, cudaFuncAttributeMaxDynamicSharedMemorySize,
                         GEMM_SMEM_BYTES);
    cudaFuncSetAttribute(attn_mma_kernel, cudaFuncAttributeMaxDynamicSharedMemorySize,
                         ATTN_SMEM_BYTES);

    // Prep: weight transpose+convert (fp16), x convert (fp16)
    transpose4_kernel<<<dim3(DMODEL / 32, DMODEL / 32, 4), dim3(32, 8)>>>(Wq, Wk, Wv, Wo);
    convert_x_kernel<<<(MTOT * DMODEL / 4) / 256, 256>>>(x);

    // QKV projections (one launch; z=0 pre-scales Q; z=2 writes V transposed)
    dim3 qkvgrid(DMODEL / 128, MTOT / 128, 3);   // (8, 32, 3)
    gemm_qkv_kernel<<<qkvgrid, 256, GEMM_SMEM_BYTES>>>(gXt, gWt, bq, bk, bv, gQ, gK, gVt);

    // Attention (fp16, register-resident P)
    dim3 agrid(SEQ / AQ, NHEADS, BATCH);         // (16, 16, 2)
    attn_mma_kernel<<<agrid, 256, ATTN_SMEM_BYTES>>>(gQ, gK, gVt, gAO);

    // Output projection (A = fp16 AO)
    dim3 ogrid(DMODEL / 128, MTOT / 128);        // (8, 32)
    gemm_out_kernel<<<ogrid, 256, GEMM_SMEM_BYTES>>>(gAO,
                                                     gWt + 3 * (size_t)(DMODEL * DMODEL / 2),
                                                     bo, out);
}

// round 17
// speedup vs baseline: 2.5481x; 1.1161x over previous
#include <cuda_runtime.h>
#include <cuda_fp16.h>
#include <cstdint>

// Problem constants (fixed by the dataset)
#define BATCH    2
#define SEQ      2048
#define DMODEL   1024
#define NHEADS   16
#define HEADDIM  64
#define MTOT     (BATCH * SEQ)

#define LOG2E 1.44269504f

// ---------------------------------------------------------------------------
// Scratch (__device__ globals) — all fp16 packed (2 halves per word)
// ---------------------------------------------------------------------------
__device__ uint32_t g_Q [BATCH * NHEADS * SEQ * HEADDIM / 2];
__device__ uint32_t g_K [BATCH * NHEADS * SEQ * HEADDIM / 2];
__device__ uint32_t g_Vt[BATCH * NHEADS * HEADDIM * SEQ / 2];
__device__ uint32_t g_AO[MTOT * DMODEL / 2];
__device__ uint32_t g_Wt[4 * DMODEL * DMODEL / 2];
__device__ uint32_t g_Xt[MTOT * DMODEL / 2];

// ---------------------------------------------------------------------------
// Helpers
// ---------------------------------------------------------------------------
__device__ __forceinline__ void mma_f16_16x8x16(float c[4], const uint32_t a[4],
                                                const uint32_t b[2]) {
    asm volatile(
        "mma.sync.aligned.m16n8k16.row.col.f32.f16.f16.f32 "
        "{%0,%1,%2,%3}, {%4,%5,%6,%7}, {%8,%9}, {%0,%1,%2,%3};"
        : "+f"(c[0]), "+f"(c[1]), "+f"(c[2]), "+f"(c[3])
        : "r"(a[0]), "r"(a[1]), "r"(a[2]), "r"(a[3]), "r"(b[0]), "r"(b[1]));
}

__device__ __forceinline__ void ldsm_x4(uint32_t r[4], uint32_t addr) {
    asm volatile("ldmatrix.sync.aligned.m8n8.x4.shared.b16 {%0,%1,%2,%3}, [%4];"
        : "=r"(r[0]), "=r"(r[1]), "=r"(r[2]), "=r"(r[3]) : "r"(addr));
}

__device__ __forceinline__ uint32_t smem_u32(const void* p) {
    uint32_t a;
    asm("{ .reg .u64 t; cvta.to.shared.u64 t, %1; cvt.u32.u64 %0, t; }" : "=r"(a) : "l"(p));
    return a;
}
__device__ __forceinline__ void cp_async16(uint32_t saddr, const void* gptr) {
    asm volatile("cp.async.ca.shared.global [%0], [%1], 16;" :: "r"(saddr), "l"(gptr));
}
__device__ __forceinline__ void cp_commit() {
    asm volatile("cp.async.commit_group;" ::: "memory");
}
template <int N> __device__ __forceinline__ void cp_wait() {
    asm volatile("cp.async.wait_group %0;" :: "n"(N) : "memory");
}
__device__ __forceinline__ uint32_t pack_h2(float a, float b) {
    __half2 h = __floats2half2_rn(a, b);
    return *(uint32_t*)&h;
}

// ---------------------------------------------------------------------------
// x -> fp16 convert (one pass)
// ---------------------------------------------------------------------------
__global__ void convert_x_kernel(const float* __restrict__ x)
{
    int idx = blockIdx.x * blockDim.x + threadIdx.x;
    float4 v = *(const float4*)(x + idx * 4);
    *(uint2*)(g_Xt + idx * 2) = make_uint2(pack_h2(v.x, v.y), pack_h2(v.z, v.w));
}

// ---------------------------------------------------------------------------
// Transpose + fp16 convert: Wt[n][k] = fp16(W[k][n]) for 4 weights
// ---------------------------------------------------------------------------
__global__ void transpose4_kernel(const float* __restrict__ W0, const float* __restrict__ W1,
                                  const float* __restrict__ W2, const float* __restrict__ W3)
{
    __shared__ float t[32][33];
    const float* src = (blockIdx.z == 0) ? W0 : (blockIdx.z == 1) ? W1
                     : (blockIdx.z == 2) ? W2 : W3;
    __half* dst = (__half*)(g_Wt + (size_t)blockIdx.z * (DMODEL * DMODEL / 2));

    int x = blockIdx.x * 32 + threadIdx.x;
    int y = blockIdx.y * 32 + threadIdx.y;
#pragma unroll
    for (int j = 0; j < 32; j += 8)
        t[threadIdx.y + j][threadIdx.x] = src[(size_t)(y + j) * DMODEL + x];
    __syncthreads();
    int x2 = blockIdx.y * 32 + threadIdx.x;
    int y2 = blockIdx.x * 32 + threadIdx.y;
#pragma unroll
    for (int j = 0; j < 32; j += 8)
        dst[(size_t)(y2 + j) * DMODEL + x2] = __float2half_rn(t[threadIdx.x][threadIdx.y + j]);
}

// ---------------------------------------------------------------------------
// fp16 GEMM mainloop (2-stage cp.async pipeline, ldmatrix fragments)
// CTA 128x128, 256 threads = 8 warps (4M x 2N), warp tile 32x64.
// NOW occupancy 2: second CTA/SM fills sync/memory bubbles.
// ---------------------------------------------------------------------------
#define KWORDS 16
#define WPAD   20
#define TILEW  (128 * WPAD)
#define GEMM_SMEM_BYTES (4 * TILEW * 4)     // 40,960 B (x2 CTAs = 80 KB/SM)

#define GEMM_PROLOG \
    extern __shared__ uint32_t smw[]; \
    const uint32_t sbase = smem_u32(smw); \
    const int tid = threadIdx.x; \
    const int wid = tid >> 5, lane = tid & 31; \
    const int gid = lane >> 2, ctid = lane & 3; \
    const int warp_m = (wid & 3) * 32, warp_n = (wid >> 2) * 64; \
    const int n0 = blockIdx.x * 128, m0 = blockIdx.y * 128; \
    const int lrow = tid >> 1, lcw = (tid & 1) * 8; \
    const int l15 = lane & 15, lhi = lane >> 4; \
    const int brow = 8 * lhi + (lane & 7), bko = ((lane >> 3) & 1) * 4;

#define GEMM_PREFETCH(st, kcw) do { \
    const uint32_t* Ab_ = A  + (size_t)(m0 + lrow) * (DMODEL / 2) + (kcw) + lcw; \
    const uint32_t* Bb_ = Bt + (size_t)(n0 + lrow) * (DMODEL / 2) + (kcw) + lcw; \
    uint32_t sa_ = sbase + ((st) * TILEW + lrow * WPAD + lcw) * 4; \
    uint32_t sb_ = sbase + ((2 + (st)) * TILEW + lrow * WPAD + lcw) * 4; \
    cp_async16(sa_,      Ab_);     \
    cp_async16(sa_ + 16, Ab_ + 4); \
    cp_async16(sb_,      Bb_);     \
    cp_async16(sb_ + 16, Bb_ + 4); \
    cp_commit(); \
} while (0)

#define GEMM_COMPUTE(st) do { \
    const uint32_t abase_ = sbase + ((st) * TILEW) * 4; \
    const uint32_t bbase_ = sbase + ((2 + (st)) * TILEW) * 4; \
    _Pragma("unroll") \
    for (int ks = 0; ks < 2; ks++) { \
        const int kb = ks * 8; \
        uint32_t afr[2][4]; \
        ldsm_x4(afr[0], abase_ + (uint32_t)((warp_m      + l15) * WPAD + kb + lhi * 4) * 4); \
        ldsm_x4(afr[1], abase_ + (uint32_t)((warp_m + 16 + l15) * WPAD + kb + lhi * 4) * 4); \
        uint32_t bfr[4][4]; \
        _Pragma("unroll") \
        for (int p = 0; p < 4; p++) \
            ldsm_x4(bfr[p], bbase_ + (uint32_t)((warp_n + p * 16 + brow) * WPAD + kb + bko) * 4); \
        _Pragma("unroll") \
        for (int i = 0; i < 2; i++) \
            _Pragma("unroll") \
            for (int p = 0; p < 4; p++) { \
                mma_f16_16x8x16(acc[i][2 * p],     afr[i], bfr[p]); \
                mma_f16_16x8x16(acc[i][2 * p + 1], afr[i], bfr[p] + 2); \
            } \
    } \
} while (0)

#define GEMM_MAINLOOP do { \
    GEMM_PREFETCH(0, 0); \
    for (int kc = 0; kc < 32; kc++) { \
        const int cur = kc & 1; \
        if (kc + 1 < 32) { GEMM_PREFETCH(cur ^ 1, (kc + 1) * KWORDS); cp_wait<1>(); } \
        else             { cp_wait<0>(); } \
        __syncthreads(); \
        GEMM_COMPUTE(cur); \
        __syncthreads(); \
    } \
} while (0)

// ---- QKV projection: grid (8, 32, 3)
//   z=0: Q packed fp16, PRE-SCALED by 0.125*log2e ; z=1: K packed fp16
//   z=2: V transposed fp16 [B,H,Hd,S]
__global__ __launch_bounds__(256, 2)
void gemm_qkv_kernel(const uint32_t* __restrict__ A, const uint32_t* __restrict__ WtBase,
                     const float* __restrict__ bq, const float* __restrict__ bk,
                     const float* __restrict__ bv,
                     uint32_t* __restrict__ Qo, uint32_t* __restrict__ Ko,
                     uint32_t* __restrict__ Vto)
{
    GEMM_PROLOG
    const int z = blockIdx.z;
    const uint32_t* Bt = WtBase + (size_t)z * (DMODEL * DMODEL / 2);
    const float* bias = (z == 0) ? bq : (z == 1) ? bk : bv;
    const float oscale = (z == 0) ? (0.125f * LOG2E) : 1.0f;

    float acc[2][8][4];
#pragma unroll
    for (int i = 0; i < 2; i++)
#pragma unroll
        for (int j = 0; j < 8; j++)
#pragma unroll
            for (int r = 0; r < 4; r++) acc[i][j][r] = 0.0f;

    GEMM_MAINLOOP;

#pragma unroll
    for (int i = 0; i < 2; i++) {
#pragma unroll
        for (int half = 0; half < 2; half++) {
            const int m = m0 + warp_m + i * 16 + gid + half * 8;
            const int b = m >> 11, s = m & 2047;
#pragma unroll
            for (int j = 0; j < 8; j++) {
                const int n = n0 + warp_n + j * 8 + ctid * 2;
                const int h = n >> 6, d0 = n & 63;
                const float v0 = (acc[i][j][half * 2 + 0] + bias[n])     * oscale;
                const float v1 = (acc[i][j][half * 2 + 1] + bias[n + 1]) * oscale;
                if (z < 2) {
                    uint32_t* C = (z == 0) ? Qo : Ko;
                    C[(((size_t)(b * NHEADS + h) * SEQ + s) << 5) + (d0 >> 1)] = pack_h2(v0, v1);
                } else {
                    __half* Vt = (__half*)Vto;
                    const size_t base = ((size_t)(b * NHEADS + h) * HEADDIM) << 11;
                    Vt[base + (size_t)d0 * SEQ + s]       = __float2half_rn(v0);
                    Vt[base + (size_t)(d0 + 1) * SEQ + s] = __float2half_rn(v1);
                }
            }
        }
    }
}

// ---- Output projection: A fp16 packed (g_AO), row-major fp32 out ----
__global__ __launch_bounds__(256, 2)
void gemm_out_kernel(const uint32_t* __restrict__ A, const uint32_t* __restrict__ Bt,
                     const float* __restrict__ bias, float* __restrict__ C)
{
    GEMM_PROLOG

    float acc[2][8][4];
#pragma unroll
    for (int i = 0; i < 2; i++)
#pragma unroll
        for (int j = 0; j < 8; j++)
#pragma unroll
            for (int r = 0; r < 4; r++) acc[i][j][r] = 0.0f;

    GEMM_MAINLOOP;

#pragma unroll
    for (int i = 0; i < 2; i++) {
#pragma unroll
        for (int half = 0; half < 2; half++) {
            const int m = m0 + warp_m + i * 16 + gid + half * 8;
#pragma unroll
            for (int j = 0; j < 8; j++) {
                const int n = n0 + warp_n + j * 8 + ctid * 2;
                float* dst = C + (size_t)m * DMODEL + n;
                dst[0] = acc[i][j][half * 2 + 0] + bias[n];
                dst[1] = acc[i][j][half * 2 + 1] + bias[n + 1];
            }
        }
    }
}

// ---------------------------------------------------------------------------
// fp16 flash attention with ALiBi — register-resident P, hoisted Q fragments,
// ldmatrix K/V, cp.async double-buffered K/V, log2-domain softmax.
// (byte-identical to round-16 passing version)
// ---------------------------------------------------------------------------
#define AQ   128
#define AK   64
#define PWD  36     // padded row stride (words)

#define QH_OFF 0                            // 128*36 = 4608
#define KH_OFF 4608                         // 2 stages x 64*36 = 2x2304
#define VH_OFF 9216                         // 2 stages x 2304
#define ATTN_SMEM_WORDS 13824
#define ATTN_SMEM_BYTES (ATTN_SMEM_WORDS * 4)   // 55,296 B

#define ATTN_PREFETCH(st, kt_) do { \
    _Pragma("unroll") \
    for (int t = 0; t < 2; t++) { \
        int idx = tid + t * 256; \
        int row = idx >> 3; \
        int w4  = (idx & 7) * 4; \
        cp_async16(sbase + (uint32_t)(KH_OFF + (st) * 2304 + row * PWD + w4) * 4, \
                   Kb + (size_t)((kt_) + row) * 32 + w4); \
        cp_async16(sbase + (uint32_t)(VH_OFF + (st) * 2304 + row * PWD + w4) * 4, \
                   Vb + (size_t)row * 1024 + ((kt_) >> 1) + w4); \
    } \
    cp_commit(); \
} while (0)

__global__ __launch_bounds__(256, 2)
void attn_mma_kernel(const uint32_t* __restrict__ Q, const uint32_t* __restrict__ K,
                     const uint32_t* __restrict__ Vt, uint32_t* __restrict__ AO)
{
    extern __shared__ uint32_t smw[];
    const uint32_t sbase = smem_u32(smw);
    uint32_t* Qh = smw + QH_OFF;

    const int tid  = threadIdx.x;
    const int wid  = tid >> 5;
    const int lane = tid & 31;
    const int gid  = lane >> 2;
    const int ctid = lane & 3;
    const int wrow = wid * 16;

    const int qt = blockIdx.x;
    const int h  = blockIdx.y;
    const int b  = blockIdx.z;
    const int q0 = qt * AQ;

    const uint32_t* Qb = Q  + (((size_t)(b * NHEADS + h) * SEQ + q0) << 5);
    const uint32_t* Kb = K  + (((size_t)(b * NHEADS + h) * SEQ) << 5);
    const uint32_t* Vb = Vt + (((size_t)(b * NHEADS + h) * HEADDIM) << 10);

    // ---- load Q tile (128 rows x 32 words) ----
#pragma unroll
    for (int t = 0; t < 4; t++) {
        int idx = tid + t * 256;
        int row = idx >> 3;
        int w4  = (idx & 7) * 4;
        *(uint4*)&Qh[row * PWD + w4] = *(const uint4*)(Qb + row * 32 + w4);
    }

    // ldmatrix lane addresses
    const int l15  = lane & 15;
    const int lhi  = lane >> 4;
    const int brow = 8 * lhi + (lane & 7);
    const int bko  = ((lane >> 3) & 1) * 4;
    const uint32_t qA = sbase + (uint32_t)(QH_OFF + (wrow + l15) * PWD + lhi * 4) * 4;
    const uint32_t kB = sbase + (uint32_t)(KH_OFF + brow * PWD + bko) * 4;
    const uint32_t vB = sbase + (uint32_t)(VH_OFF + brow * PWD + bko) * 4;

    __syncthreads();
    // ---- hoist Q fragments into registers (whole kernel) ----
    uint32_t qfrag[4][4];
#pragma unroll
    for (int ks = 0; ks < 4; ks++)
        ldsm_x4(qfrag[ks], qA + ks * 32);

    const float slope2 = exp2f(-(float)h / (float)NHEADS) * LOG2E;
    float bc0[8], bc1[8];
#pragma unroll
    for (int nt = 0; nt < 8; nt++) {
        bc0[nt] = slope2 * (float)(nt * 8 + 2 * ctid);
        bc1[nt] = bc0[nt] + slope2;
    }

    float oacc[8][4];
#pragma unroll
    for (int j = 0; j < 8; j++)
#pragma unroll
        for (int r = 0; r < 4; r++) oacc[j][r] = 0.0f;
    float m0 = -1e30f, m1 = -1e30f, l0 = 0.0f, l1 = 0.0f;

    ATTN_PREFETCH(0, 0);

    for (int c = 0; c < 32; c++) {
        const int kt = c * AK;
        const int cur = c & 1;
        if (c + 1 < 32) { ATTN_PREFETCH(cur ^ 1, kt + AK); cp_wait<1>(); }
        else            { cp_wait<0>(); }
        __syncthreads();

        const uint32_t kBs = kB + (uint32_t)(cur * 2304 * 4);
        const uint32_t vBs = vB + (uint32_t)(cur * 2304 * 4);

        // ---- S = Q K^T ----
        float sacc[8][4];
#pragma unroll
        for (int j = 0; j < 8; j++)
#pragma unroll
            for (int r = 0; r < 4; r++) sacc[j][r] = 0.0f;

#pragma unroll
        for (int ks = 0; ks < 4; ks++) {
#pragma unroll
            for (int p = 0; p < 4; p++) {
                uint32_t bb[4];
                ldsm_x4(bb, kBs + (uint32_t)(p * 16 * PWD * 4) + ks * 32);
                mma_f16_16x8x16(sacc[2 * p],     qfrag[ks], bb);
                mma_f16_16x8x16(sacc[2 * p + 1], qfrag[ks], bb + 2);
            }
        }

        // ---- ALiBi (k-term, log2 domain) in place + row max ----
        float mx0 = -1e30f, mx1 = -1e30f;
#pragma unroll
        for (int nt = 0; nt < 8; nt++) {
            sacc[nt][0] += bc0[nt];
            sacc[nt][1] += bc1[nt];
            sacc[nt][2] += bc0[nt];
            sacc[nt][3] += bc1[nt];
            mx0 = fmaxf(mx0, fmaxf(sacc[nt][0], sacc[nt][1]));
            mx1 = fmaxf(mx1, fmaxf(sacc[nt][2], sacc[nt][3]));
        }
#pragma unroll
        for (int msk = 1; msk < 4; msk <<= 1) {
            mx0 = fmaxf(mx0, __shfl_xor_sync(0xffffffffu, mx0, msk));
            mx1 = fmaxf(mx1, __shfl_xor_sync(0xffffffffu, mx1, msk));
        }

        const float kbias = slope2 * (float)kt;
        const float m0n = fmaxf(m0, mx0 + kbias);
        const float m1n = fmaxf(m1, mx1 + kbias);
        const float corr0 = exp2f(m0 - m0n);
        const float corr1 = exp2f(m1 - m1n);
        m0 = m0n; m1 = m1n;
        const float mm0 = m0 - kbias;
        const float mm1 = m1 - kbias;

        // ---- P = exp2(sacc - mm) packed DIRECTLY into PV A-fragments ----
        uint32_t pf[8][2];
        float ps0 = 0.0f, ps1 = 0.0f;
#pragma unroll
        for (int nt = 0; nt < 8; nt++) {
            float p0 = exp2f(sacc[nt][0] - mm0);
            float p1 = exp2f(sacc[nt][1] - mm0);
            float p2 = exp2f(sacc[nt][2] - mm1);
            float p3 = exp2f(sacc[nt][3] - mm1);
            ps0 += p0 + p1;
            ps1 += p2 + p3;
            pf[nt][0] = pack_h2(p0, p1);
            pf[nt][1] = pack_h2(p2, p3);
        }
#pragma unroll
        for (int msk = 1; msk < 4; msk <<= 1) {
            ps0 += __shfl_xor_sync(0xffffffffu, ps0, msk);
            ps1 += __shfl_xor_sync(0xffffffffu, ps1, msk);
        }
        l0 = l0 * corr0 + ps0;
        l1 = l1 * corr1 + ps1;

#pragma unroll
        for (int nt = 0; nt < 8; nt++) {
            oacc[nt][0] *= corr0; oacc[nt][1] *= corr0;
            oacc[nt][2] *= corr1; oacc[nt][3] *= corr1;
        }

        // ---- O += P V : A from registers (pf), B via ldmatrix ----
#pragma unroll
        for (int ks = 0; ks < 4; ks++) {
            uint32_t a[4];
            a[0] = pf[2 * ks][0];
            a[1] = pf[2 * ks][1];
            a[2] = pf[2 * ks + 1][0];
            a[3] = pf[2 * ks + 1][1];
#pragma unroll
            for (int p = 0; p < 4; p++) {
                uint32_t bb[4];
                ldsm_x4(bb, vBs + (uint32_t)(p * 16 * PWD * 4) + ks * 32);
                mma_f16_16x8x16(oacc[2 * p],     a, bb);
                mma_f16_16x8x16(oacc[2 * p + 1], a, bb + 2);
            }
        }
        __syncthreads();   // done reading stage cur before it is refilled
    }

    // ---- normalize, pack fp16, write AO [m][D/2 words] ----
    const float inv0 = 1.0f / l0;
    const float inv1 = 1.0f / l1;
    const int qr0 = q0 + wrow + gid;
    const int qr1 = qr0 + 8;
    uint32_t* dst0 = AO + (((size_t)(b * SEQ + qr0)) << 9) + h * 32;
    uint32_t* dst1 = AO + (((size_t)(b * SEQ + qr1)) << 9) + h * 32;
#pragma unroll
    for (int nt = 0; nt < 8; nt++) {
        dst0[nt * 4 + ctid] = pack_h2(oacc[nt][0] * inv0, oacc[nt][1] * inv0);
        dst1[nt * 4 + ctid] = pack_h2(oacc[nt][2] * inv1, oacc[nt][3] * inv1);
    }
}

// ---------------------------------------------------------------------------
// Launcher
// ---------------------------------------------------------------------------
extern "C" void kernel_launch(void* const* d_in, const int* in_sizes, int n_in,
                              void* d_out, int out_size)
{
    const float* x  = (const float*)d_in[0];
    const float* Wq = (const float*)d_in[1];
    const float* bq = (const float*)d_in[2];
    const float* Wk = (const float*)d_in[3];
    const float* bk = (const float*)d_in[4];
    const float* Wv = (const float*)d_in[5];
    const float* bv = (const float*)d_in[6];
    const float* Wo = (const float*)d_in[7];
    const float* bo = (const float*)d_in[8];
    float* out = (float*)d_out;

    uint32_t *gQ, *gK, *gVt, *gAO, *gWt, *gXt;
    cudaGetSymbolAddress((void**)&gQ,  g_Q);
    cudaGetSymbolAddress((void**)&gK,  g_K);
    cudaGetSymbolAddress((void**)&gVt, g_Vt);
    cudaGetSymbolAddress((void**)&gAO, g_AO);
    cudaGetSymbolAddress((void**)&gWt, g_Wt);
    cudaGetSymbolAddress((void**)&gXt, g_Xt);

    cudaFuncSetAttribute(gemm_qkv_kernel, cudaFuncAttributeMaxDynamicSharedMemorySize,
                         GEMM_SMEM_BYTES);
    cudaFuncSetAttribute(gemm_out_kernel, cudaFuncAttributeMaxDynamicSharedMemorySize,
                         GEMM_SMEM_BYTES);
    cudaFuncSetAttribute(attn_mma_kernel, cudaFuncAttributeMaxDynamicSharedMemorySize,
                         ATTN_SMEM_BYTES);

    // Prep: weight transpose+convert (fp16), x convert (fp16)
    transpose4_kernel<<<dim3(DMODEL / 32, DMODEL / 32, 4), dim3(32, 8)>>>(Wq, Wk, Wv, Wo);
    convert_x_kernel<<<(MTOT * DMODEL / 4) / 256, 256>>>(x);

    // QKV projections (one launch; z=0 pre-scales Q; z=2 writes V transposed)
    dim3 qkvgrid(DMODEL / 128, MTOT / 128, 3);   // (8, 32, 3)
    gemm_qkv_kernel<<<qkvgrid, 256, GEMM_SMEM_BYTES>>>(gXt, gWt, bq, bk, bv, gQ, gK, gVt);

    // Attention (fp16, register-resident P)
    dim3 agrid(SEQ / AQ, NHEADS, BATCH);         // (16, 16, 2)
    attn_mma_kernel<<<agrid, 256, ATTN_SMEM_BYTES>>>(gQ, gK, gVt, gAO);

    // Output projection (A = fp16 AO)
    dim3 ogrid(DMODEL / 128, MTOT / 128);        // (8, 32)
    gemm_out_kernel<<<ogrid, 256, GEMM_SMEM_BYTES>>>(gAO,
                                                     gWt + 3 * (size_t)(DMODEL * DMODEL / 2),
                                                     bo, out);
}